// round 9
// baseline (speedup 1.0000x reference)
#include <cuda_runtime.h>

#define NN   50000
#define EE   300000
#define PP   200000
#define IND  480
#define HD   256
#define HIDD 128

// ---------------- scratch (device globals) ----------------------------------
__device__ float g_h[(size_t)NN * HD];
__device__ float g_tmp[(size_t)NN * HD];
__device__ float g_mean[(size_t)NN * HD];
__device__ float g_z1[(size_t)PP * HIDD];
__device__ float g_z2[(size_t)PP * HIDD];
__device__ int   g_cnt[NN];
__device__ int   g_off[NN + 1];
__device__ int   g_cur[NN];
__device__ int   g_csr[EE];

// split x into tf32-truncated hi + exact remainder lo (HMMA.TF32 ignores the
// low 13 mantissa bits of a .b32 operand, so masking is a valid tf32 convert)
__device__ __forceinline__ uint2 split2(float x) {
    unsigned hx = __float_as_uint(x) & 0xffffe000u;
    float lo = x - __uint_as_float(hx);
    return make_uint2(hx, __float_as_uint(lo));
}

// ---------------- 3xTF32 tensor-core GEMM -----------------------------------
// C[M,Nc] = act( A@B + bias (+ A2@B2 + bias2 if DUAL) )
// FEAT: logical A row p = concat(|H[i_p]-H[j_p]|, H[i_p]*H[j_p]), K = 2*HD.
// Requires K%16==0, Nc%128==0.
template <bool RELU, bool DUAL, bool FEAT>
__global__ __launch_bounds__(256) void mma_gemm(
    const float* __restrict__ A, const float* __restrict__ B,
    const float* __restrict__ bias,
    const float* __restrict__ A2, const float* __restrict__ B2,
    const float* __restrict__ bias2,
    const int* __restrict__ iidx, const int* __restrict__ jidx,
    float* __restrict__ C, int M, int Nc, int K)
{
    constexpr int BM = 128, BN = 128, BK = 16;
    constexpr int PA = BK + 4;    // uint2 pitch 20
    constexpr int PB = BN + 4;    // uint2 pitch 132 (264 words ≡ 8 mod 32:
                                  // fragment LDS.64 loads are conflict-free)
    __shared__ uint2 As[BM][PA];  // (hi, lo) interleaved
    __shared__ uint2 Bs[BK][PB];

    const int tid  = threadIdx.x;
    const int warp = tid >> 5, lane = tid & 31;
    const int group = lane >> 2, tig = lane & 3;
    const int wm = (warp & 3) * 32, wn = (warp >> 2) * 64;
    const int bm = blockIdx.y * BM, bn = blockIdx.x * BN;

    const int kIters = K / BK;
    const int nIter = (DUAL ? 2 : 1) * kIters;

    // A-loader geometry (fixed per thread)
    const int am = tid >> 1, akq = (tid & 1) * 8;
    const int arow = bm + am;
    int ia = 0, jb = 0;
    if (FEAT && arow < M) { ia = iidx[arow]; jb = jidx[arow]; }
    // B-loader geometry
    const int bkr = tid >> 4, bn8 = (tid & 15) * 8;

    float ra[8], rb[8];

    auto loadA = [&](int it) {
        int part = DUAL ? (it / kIters) : 0;
        int k0 = (it - part * kIters) * BK;
#pragma unroll
        for (int q = 0; q < 8; ++q) ra[q] = 0.f;
        if (arow < M) {
            if (FEAT) {
                const float* Ha = A + (size_t)ia * HD;
                const float* Hb = A + (size_t)jb * HD;
                int k = k0 + akq;
#pragma unroll
                for (int q = 0; q < 2; ++q) {
                    int kk = k + q * 4;
                    float4 r;
                    if (kk < HD) {
                        float4 xa = *(const float4*)(Ha + kk);
                        float4 xb = *(const float4*)(Hb + kk);
                        r = make_float4(fabsf(xa.x - xb.x), fabsf(xa.y - xb.y),
                                        fabsf(xa.z - xb.z), fabsf(xa.w - xb.w));
                    } else {
                        float4 xa = *(const float4*)(Ha + kk - HD);
                        float4 xb = *(const float4*)(Hb + kk - HD);
                        r = make_float4(xa.x * xb.x, xa.y * xb.y,
                                        xa.z * xb.z, xa.w * xb.w);
                    }
                    ra[q * 4 + 0] = r.x; ra[q * 4 + 1] = r.y;
                    ra[q * 4 + 2] = r.z; ra[q * 4 + 3] = r.w;
                }
            } else {
                const float* Ap = (DUAL && part) ? A2 : A;
                const float* p = Ap + (size_t)arow * K + k0 + akq;
                float4 v0 = *(const float4*)p;
                float4 v1 = *(const float4*)(p + 4);
                ra[0] = v0.x; ra[1] = v0.y; ra[2] = v0.z; ra[3] = v0.w;
                ra[4] = v1.x; ra[5] = v1.y; ra[6] = v1.z; ra[7] = v1.w;
            }
        }
    };

    auto loadB = [&](int it) {
        int part = DUAL ? (it / kIters) : 0;
        int k0 = (it - part * kIters) * BK;
        const float* Bp = (DUAL && part) ? B2 : B;
        const float* p = Bp + (size_t)(k0 + bkr) * Nc + bn + bn8;
        float4 v0 = *(const float4*)p;
        float4 v1 = *(const float4*)(p + 4);
        rb[0] = v0.x; rb[1] = v0.y; rb[2] = v0.z; rb[3] = v0.w;
        rb[4] = v1.x; rb[5] = v1.y; rb[6] = v1.z; rb[7] = v1.w;
    };

    float c[2][8][4] = {};

    loadA(0);
    loadB(0);

    for (int it = 0; it < nIter; ++it) {
        // ---- split + store current tile to smem ----
        {
            uint2 s[8];
#pragma unroll
            for (int q = 0; q < 8; ++q) s[q] = split2(ra[q]);
            uint4* dp = (uint4*)&As[am][akq];
            dp[0] = make_uint4(s[0].x, s[0].y, s[1].x, s[1].y);
            dp[1] = make_uint4(s[2].x, s[2].y, s[3].x, s[3].y);
            dp[2] = make_uint4(s[4].x, s[4].y, s[5].x, s[5].y);
            dp[3] = make_uint4(s[6].x, s[6].y, s[7].x, s[7].y);
        }
        {
            uint2 s[8];
#pragma unroll
            for (int q = 0; q < 8; ++q) s[q] = split2(rb[q]);
            uint4* dp = (uint4*)&Bs[bkr][bn8];
            dp[0] = make_uint4(s[0].x, s[0].y, s[1].x, s[1].y);
            dp[1] = make_uint4(s[2].x, s[2].y, s[3].x, s[3].y);
            dp[2] = make_uint4(s[4].x, s[4].y, s[5].x, s[5].y);
            dp[3] = make_uint4(s[6].x, s[6].y, s[7].x, s[7].y);
        }
        __syncthreads();

        // ---- prefetch next tile into registers (overlaps with MMA below) ----
        if (it + 1 < nIter) { loadA(it + 1); loadB(it + 1); }

        // ---- compute ----
#pragma unroll
        for (int ks = 0; ks < BK; ks += 8) {
            uint2 af[2][4];
#pragma unroll
            for (int i = 0; i < 2; ++i) {
                int r = wm + i * 16 + group;
                af[i][0] = As[r][ks + tig];
                af[i][1] = As[r + 8][ks + tig];
                af[i][2] = As[r][ks + tig + 4];
                af[i][3] = As[r + 8][ks + tig + 4];
            }
            uint2 bf[8][2];
#pragma unroll
            for (int j = 0; j < 8; ++j) {
                int nc_ = wn + j * 8 + group;
                bf[j][0] = Bs[ks + tig][nc_];
                bf[j][1] = Bs[ks + tig + 4][nc_];
            }
#pragma unroll
            for (int i = 0; i < 2; ++i)
#pragma unroll
                for (int j = 0; j < 8; ++j) {
                    // hi * hi
                    asm volatile(
                        "mma.sync.aligned.m16n8k8.row.col.f32.tf32.tf32.f32 "
                        "{%0,%1,%2,%3},{%4,%5,%6,%7},{%8,%9},{%0,%1,%2,%3};"
                        : "+f"(c[i][j][0]), "+f"(c[i][j][1]),
                          "+f"(c[i][j][2]), "+f"(c[i][j][3])
                        : "r"(af[i][0].x), "r"(af[i][1].x), "r"(af[i][2].x), "r"(af[i][3].x),
                          "r"(bf[j][0].x), "r"(bf[j][1].x));
                    // lo * hi
                    asm volatile(
                        "mma.sync.aligned.m16n8k8.row.col.f32.tf32.tf32.f32 "
                        "{%0,%1,%2,%3},{%4,%5,%6,%7},{%8,%9},{%0,%1,%2,%3};"
                        : "+f"(c[i][j][0]), "+f"(c[i][j][1]),
                          "+f"(c[i][j][2]), "+f"(c[i][j][3])
                        : "r"(af[i][0].y), "r"(af[i][1].y), "r"(af[i][2].y), "r"(af[i][3].y),
                          "r"(bf[j][0].x), "r"(bf[j][1].x));
                    // hi * lo
                    asm volatile(
                        "mma.sync.aligned.m16n8k8.row.col.f32.tf32.tf32.f32 "
                        "{%0,%1,%2,%3},{%4,%5,%6,%7},{%8,%9},{%0,%1,%2,%3};"
                        : "+f"(c[i][j][0]), "+f"(c[i][j][1]),
                          "+f"(c[i][j][2]), "+f"(c[i][j][3])
                        : "r"(af[i][0].x), "r"(af[i][1].x), "r"(af[i][2].x), "r"(af[i][3].x),
                          "r"(bf[j][0].y), "r"(bf[j][1].y));
                }
        }
        __syncthreads();
    }

    // ---- epilogue ----
#pragma unroll
    for (int i = 0; i < 2; ++i) {
        int r0 = bm + wm + i * 16 + group;
#pragma unroll
        for (int j = 0; j < 8; ++j) {
            int col = bn + wn + j * 8 + tig * 2;
            float bb0 = bias[col], bb1 = bias[col + 1];
            if (DUAL) { bb0 += bias2[col]; bb1 += bias2[col + 1]; }
            if (r0 < M) {
                float v0 = c[i][j][0] + bb0, v1 = c[i][j][1] + bb1;
                if (RELU) { v0 = fmaxf(v0, 0.f); v1 = fmaxf(v1, 0.f); }
                C[(size_t)r0 * Nc + col] = v0;
                C[(size_t)r0 * Nc + col + 1] = v1;
            }
            if (r0 + 8 < M) {
                float v2 = c[i][j][2] + bb0, v3 = c[i][j][3] + bb1;
                if (RELU) { v2 = fmaxf(v2, 0.f); v3 = fmaxf(v3, 0.f); }
                C[(size_t)(r0 + 8) * Nc + col] = v2;
                C[(size_t)(r0 + 8) * Nc + col + 1] = v3;
            }
        }
    }
}

// ---------------- CSR build --------------------------------------------------
__global__ __launch_bounds__(256) void count_kernel(const int* __restrict__ dst,
                                                    int* __restrict__ cnt)
{
    int e = blockIdx.x * blockDim.x + threadIdx.x;
    if (e < EE) atomicAdd(&cnt[dst[e]], 1);
}

__global__ __launch_bounds__(1024) void scan_kernel(const int* __restrict__ cnt,
                                                    int* __restrict__ off,
                                                    int* __restrict__ cur)
{
    __shared__ int sh[1024];
    __shared__ int carry;
    int t = threadIdx.x;
    if (t == 0) carry = 0;
    __syncthreads();
    for (int base = 0; base < NN; base += 1024) {
        int i = base + t;
        int v = (i < NN) ? cnt[i] : 0;
        sh[t] = v;
        __syncthreads();
        for (int o = 1; o < 1024; o <<= 1) {
            int x = (t >= o) ? sh[t - o] : 0;
            __syncthreads();
            sh[t] += x;
            __syncthreads();
        }
        int excl = sh[t] - v;
        if (i < NN) { off[i] = carry + excl; cur[i] = carry + excl; }
        __syncthreads();
        if (t == 0) carry += sh[1023];
        __syncthreads();
    }
    if (t == 0) off[NN] = carry;
}

__global__ __launch_bounds__(256) void fill_kernel(const int* __restrict__ src,
                                                   const int* __restrict__ dst,
                                                   int* __restrict__ cur,
                                                   int* __restrict__ csr)
{
    int e = blockIdx.x * blockDim.x + threadIdx.x;
    if (e < EE) {
        int d = dst[e];
        int pos = atomicAdd(&cur[d], 1);
        csr[pos] = src[e];
    }
}

// ---------------- neighbor mean (warp per node, CSR gather) ------------------
__global__ __launch_bounds__(256) void agg_kernel(
    const int* __restrict__ off, const int* __restrict__ csr,
    const float* __restrict__ h, float* __restrict__ mean)
{
    int n = blockIdx.x * 8 + (threadIdx.x >> 5);
    if (n >= NN) return;
    int lane = threadIdx.x & 31;
    int s0 = off[n], s1 = off[n + 1];
    float4 a0 = make_float4(0.f, 0.f, 0.f, 0.f), a1 = a0;
    for (int e = s0; e < s1; ++e) {
        int s = csr[e];
        const float4* hp = (const float4*)(h + (size_t)s * HD);
        float4 v0 = hp[lane], v1 = hp[lane + 32];
        a0.x += v0.x; a0.y += v0.y; a0.z += v0.z; a0.w += v0.w;
        a1.x += v1.x; a1.y += v1.y; a1.z += v1.z; a1.w += v1.w;
    }
    float inv = 1.f / (float)max(s1 - s0, 1);
    a0.x *= inv; a0.y *= inv; a0.z *= inv; a0.w *= inv;
    a1.x *= inv; a1.y *= inv; a1.z *= inv; a1.w *= inv;
    float4* mp = (float4*)(mean + (size_t)n * HD);
    mp[lane] = a0;
    mp[lane + 32] = a1;
}

// ---------------- fused ReLU + LayerNorm (warp per row, H=256) ---------------
__global__ __launch_bounds__(256) void relu_ln_kernel(
    const float* __restrict__ X, float* __restrict__ Y,
    const float* __restrict__ gamma, const float* __restrict__ beta, int M)
{
    int row = blockIdx.x * 8 + (threadIdx.x >> 5);
    if (row >= M) return;
    int lane = threadIdx.x & 31;
    const float* x = X + (size_t)row * HD;
    float v[8];
    float s = 0.f;
#pragma unroll
    for (int i = 0; i < 8; ++i) { v[i] = fmaxf(x[lane + 32 * i], 0.f); s += v[i]; }
#pragma unroll
    for (int o = 16; o; o >>= 1) s += __shfl_xor_sync(0xffffffffu, s, o);
    float mu = s * (1.f / HD);
    float q = 0.f;
#pragma unroll
    for (int i = 0; i < 8; ++i) { float d = v[i] - mu; q += d * d; }
#pragma unroll
    for (int o = 16; o; o >>= 1) q += __shfl_xor_sync(0xffffffffu, q, o);
    float rstd = rsqrtf(q * (1.f / HD) + 1e-5f);
    float* y = Y + (size_t)row * HD;
#pragma unroll
    for (int i = 0; i < 8; ++i) {
        int c = lane + 32 * i;
        y[c] = (v[i] - mu) * rstd * gamma[c] + beta[c];
    }
}

// ---------------- L2 row-normalize ------------------------------------------
__global__ __launch_bounds__(256) void l2norm_kernel(
    const float* __restrict__ X, float* __restrict__ Y, int M)
{
    int row = blockIdx.x * 8 + (threadIdx.x >> 5);
    if (row >= M) return;
    int lane = threadIdx.x & 31;
    const float* x = X + (size_t)row * HD;
    float v[8];
    float s = 0.f;
#pragma unroll
    for (int i = 0; i < 8; ++i) { v[i] = x[lane + 32 * i]; s += v[i] * v[i]; }
#pragma unroll
    for (int o = 16; o; o >>= 1) s += __shfl_xor_sync(0xffffffffu, s, o);
    float sc = 1.f / fmaxf(sqrtf(s), 1e-12f);
    float* y = Y + (size_t)row * HD;
#pragma unroll
    for (int i = 0; i < 8; ++i) y[lane + 32 * i] = v[i] * sc;
}

// ---------------- final logits ----------------------------------------------
__global__ __launch_bounds__(256) void logits_kernel(
    const float* __restrict__ z2, const float* __restrict__ W3,
    const float* __restrict__ b3, float* __restrict__ out)
{
    int p = blockIdx.x * 8 + (threadIdx.x >> 5);
    if (p >= PP) return;
    int lane = threadIdx.x & 31;
    const float* z = z2 + (size_t)p * HIDD;
    float s = 0.f;
#pragma unroll
    for (int i = 0; i < 4; ++i) { int c = lane + 32 * i; s += z[c] * W3[c]; }
#pragma unroll
    for (int o = 16; o; o >>= 1) s += __shfl_xor_sync(0xffffffffu, s, o);
    if (lane == 0) out[p] = s + b3[0];
}

// ---------------- launch ----------------------------------------------------
extern "C" void kernel_launch(void* const* d_in, const int* in_sizes, int n_in,
                              void* d_out, int out_size)
{
    const float* X       = (const float*)d_in[0];
    const int*   edge    = (const int*)d_in[1];
    const int*   i_idx   = (const int*)d_in[2];
    const int*   j_idx   = (const int*)d_in[3];
    const float* W_in    = (const float*)d_in[4];
    const float* b_in    = (const float*)d_in[5];
    const float* Ws_self = (const float*)d_in[6];
    const float* bs_self = (const float*)d_in[7];
    const float* Ws_nei  = (const float*)d_in[8];
    const float* bs_nei  = (const float*)d_in[9];
    const float* gammas  = (const float*)d_in[10];
    const float* betas   = (const float*)d_in[11];
    const float* W1      = (const float*)d_in[12];
    const float* b1      = (const float*)d_in[13];
    const float* W2      = (const float*)d_in[14];
    const float* b2      = (const float*)d_in[15];
    const float* W3      = (const float*)d_in[16];
    const float* b3      = (const float*)d_in[17];

    const int* src = edge;
    const int* dst = edge + EE;

    float *h, *tmp, *mean, *z1, *z2;
    int *cnt, *off, *cur, *csr;
    cudaGetSymbolAddress((void**)&h,    g_h);
    cudaGetSymbolAddress((void**)&tmp,  g_tmp);
    cudaGetSymbolAddress((void**)&mean, g_mean);
    cudaGetSymbolAddress((void**)&z1,   g_z1);
    cudaGetSymbolAddress((void**)&z2,   g_z2);
    cudaGetSymbolAddress((void**)&cnt,  g_cnt);
    cudaGetSymbolAddress((void**)&off,  g_off);
    cudaGetSymbolAddress((void**)&cur,  g_cur);
    cudaGetSymbolAddress((void**)&csr,  g_csr);

    float* outH = (float*)d_out;
    float* outL = outH + (size_t)NN * HD;

    dim3 blk(256);

    // 1) encoder: h = relu(X @ W_in + b_in)
    mma_gemm<true, false, false><<<dim3(HD / 128, (NN + 127) / 128), blk>>>(
        X, W_in, b_in, nullptr, nullptr, nullptr, nullptr, nullptr,
        h, NN, HD, IND);

    // 2) CSR build
    cudaMemsetAsync(cnt, 0, NN * sizeof(int));
    count_kernel<<<(EE + 255) / 256, blk>>>(dst, cnt);
    scan_kernel<<<1, 1024>>>(cnt, off, cur);
    fill_kernel<<<(EE + 255) / 256, blk>>>(src, dst, cur, csr);

    // 3) GNN layers
    for (int l = 0; l < 3; ++l) {
        agg_kernel<<<(NN + 7) / 8, blk>>>(off, csr, h, mean);
        mma_gemm<false, true, false><<<dim3(HD / 128, (NN + 127) / 128), blk>>>(
            h, Ws_self + (size_t)l * HD * HD, bs_self + (size_t)l * HD,
            mean, Ws_nei + (size_t)l * HD * HD, bs_nei + (size_t)l * HD,
            nullptr, nullptr, tmp, NN, HD, HD);
        relu_ln_kernel<<<(NN + 7) / 8, blk>>>(tmp, h, gammas + (size_t)l * HD,
                                              betas + (size_t)l * HD, NN);
    }

    // 4) H = l2-normalize(h)
    l2norm_kernel<<<(NN + 7) / 8, blk>>>(h, outH, NN);

    // 5) edge head (feat fused into GEMM1 A-loader)
    mma_gemm<true, false, true><<<dim3(HIDD / 128, (PP + 127) / 128), blk>>>(
        outH, W1, b1, nullptr, nullptr, nullptr, i_idx, j_idx,
        z1, PP, HIDD, 2 * HD);
    mma_gemm<true, false, false><<<dim3(HIDD / 128, (PP + 127) / 128), blk>>>(
        z1, W2, b2, nullptr, nullptr, nullptr, nullptr, nullptr,
        z2, PP, HIDD, HIDD);
    logits_kernel<<<(PP + 7) / 8, blk>>>(z2, W3, b3, outL);
}

// round 10
// speedup vs baseline: 1.8616x; 1.8616x over previous
#include <cuda_runtime.h>

#define NN   50000
#define EE   300000
#define PP   200000
#define IND  480
#define HD   256
#define HIDD 128

// ---------------- scratch (device globals) ----------------------------------
__device__ float g_h[(size_t)NN * HD];
__device__ float g_tmp[(size_t)NN * HD];
__device__ float g_mean[(size_t)NN * HD];
__device__ float g_z1[(size_t)PP * HIDD];
__device__ float g_z2[(size_t)PP * HIDD];
__device__ int   g_cnt[NN];
__device__ int   g_off[NN + 1];
__device__ int   g_cur[NN];
__device__ int   g_csr[EE];

// pack two fp32 into (bf16x2 hi-pair, bf16x2 lo-pair): x ≈ hi + lo with
// |x - hi - lo| <~ 2^-18 |x|. Low half of each word = x0, high half = x1.
__device__ __forceinline__ uint2 bsplit2(float x0, float x1) {
    unsigned hp;
    asm("cvt.rn.bf16x2.f32 %0, %1, %2;" : "=r"(hp) : "f"(x1), "f"(x0));
    float h0 = __uint_as_float(hp << 16);
    float h1 = __uint_as_float(hp & 0xffff0000u);
    unsigned lp;
    asm("cvt.rn.bf16x2.f32 %0, %1, %2;" : "=r"(lp) : "f"(x1 - h1), "f"(x0 - h0));
    return make_uint2(hp, lp);
}

// ---------------- 3-term bf16 tensor-core GEMM ------------------------------
// C[M,Nc] = act( A@B + bias (+ A2@B2 + bias2 if DUAL) )
// FEAT: logical A row p = concat(|H[i_p]-H[j_p]|, H[i_p]*H[j_p]), K = 2*HD.
// Requires K%16==0, Nc%128==0.
template <bool RELU, bool DUAL, bool FEAT>
__global__ __launch_bounds__(256) void mma_gemm(
    const float* __restrict__ A, const float* __restrict__ B,
    const float* __restrict__ bias,
    const float* __restrict__ A2, const float* __restrict__ B2,
    const float* __restrict__ bias2,
    const int* __restrict__ iidx, const int* __restrict__ jidx,
    float* __restrict__ C, int M, int Nc, int K)
{
    constexpr int BM = 128, BN = 128, BK = 16;
    constexpr int PA = 12;    // uint2/row (8 kpairs + 4 pad): 2PA=24 mod 32 ->
                              // A-frag LDS.64 conflict-free per half-warp
    constexpr int PB = 132;   // uint2/row (128 cols + 4 pad): 2PB=8 mod 32 ->
                              // B-frag LDS.64 conflict-free per half-warp
    __shared__ uint2 As[BM][PA];   // [row][kpair] = (hi-pair, lo-pair)
    __shared__ uint2 Bs[BK / 2][PB];  // [kpair][col]

    const int tid  = threadIdx.x;
    const int warp = tid >> 5, lane = tid & 31;
    const int group = lane >> 2, tig = lane & 3;
    const int wm = (warp & 3) * 32, wn = (warp >> 2) * 64;
    const int bm = blockIdx.y * BM, bn = blockIdx.x * BN;

    const int kIters = K / BK;
    const int nIter = (DUAL ? 2 : 1) * kIters;

    // A loader: row am, k-offset akq (0 or 8)
    const int am = tid >> 1, akq = (tid & 1) * 8;
    const int arow = bm + am;
    int ia = 0, jb = 0;
    if (FEAT && arow < M) { ia = iidx[arow]; jb = jidx[arow]; }
    // B loader: kpair row bkp (0..7), 4 cols starting at bc0
    const int bkp = tid >> 5;
    const int bc0 = (tid & 31) * 4;

    float c[2][8][4] = {};

    for (int it = 0; it < nIter; ++it) {
        const int part = DUAL ? (it / kIters) : 0;
        const int k0 = (it - part * kIters) * BK;

        // ---- load A rows (8 floats), split, store ----
        {
            float ra[8];
#pragma unroll
            for (int q = 0; q < 8; ++q) ra[q] = 0.f;
            if (arow < M) {
                if (FEAT) {
                    const float* Ha = A + (size_t)ia * HD;
                    const float* Hb = A + (size_t)jb * HD;
                    int k = k0 + akq;
#pragma unroll
                    for (int q = 0; q < 2; ++q) {
                        int kk = k + q * 4;
                        float4 r;
                        if (kk < HD) {
                            float4 xa = *(const float4*)(Ha + kk);
                            float4 xb = *(const float4*)(Hb + kk);
                            r = make_float4(fabsf(xa.x - xb.x), fabsf(xa.y - xb.y),
                                            fabsf(xa.z - xb.z), fabsf(xa.w - xb.w));
                        } else {
                            float4 xa = *(const float4*)(Ha + kk - HD);
                            float4 xb = *(const float4*)(Hb + kk - HD);
                            r = make_float4(xa.x * xb.x, xa.y * xb.y,
                                            xa.z * xb.z, xa.w * xb.w);
                        }
                        ra[q * 4 + 0] = r.x; ra[q * 4 + 1] = r.y;
                        ra[q * 4 + 2] = r.z; ra[q * 4 + 3] = r.w;
                    }
                } else {
                    const float* Ap = (DUAL && part) ? A2 : A;
                    const float* p = Ap + (size_t)arow * K + k0 + akq;
                    float4 v0 = *(const float4*)p;
                    float4 v1 = *(const float4*)(p + 4);
                    ra[0] = v0.x; ra[1] = v0.y; ra[2] = v0.z; ra[3] = v0.w;
                    ra[4] = v1.x; ra[5] = v1.y; ra[6] = v1.z; ra[7] = v1.w;
                }
            }
            uint2 s0 = bsplit2(ra[0], ra[1]);
            uint2 s1 = bsplit2(ra[2], ra[3]);
            uint2 s2 = bsplit2(ra[4], ra[5]);
            uint2 s3 = bsplit2(ra[6], ra[7]);
            uint4* dp = (uint4*)&As[am][(tid & 1) * 4];
            dp[0] = make_uint4(s0.x, s0.y, s1.x, s1.y);
            dp[1] = make_uint4(s2.x, s2.y, s3.x, s3.y);
        }
        // ---- load B k-pair rows (2 rows x 4 cols), split, store ----
        {
            const float* Bp = (DUAL && part) ? B2 : B;
            const float* p0 = Bp + (size_t)(k0 + 2 * bkp) * Nc + bn + bc0;
            const float* p1 = p0 + Nc;
            float4 r0 = *(const float4*)p0;   // k even, cols c..c+3
            float4 r1 = *(const float4*)p1;   // k odd
            uint2 s0 = bsplit2(r0.x, r1.x);
            uint2 s1 = bsplit2(r0.y, r1.y);
            uint2 s2 = bsplit2(r0.z, r1.z);
            uint2 s3 = bsplit2(r0.w, r1.w);
            uint4* dp = (uint4*)&Bs[bkp][bc0];
            dp[0] = make_uint4(s0.x, s0.y, s1.x, s1.y);
            dp[1] = make_uint4(s2.x, s2.y, s3.x, s3.y);
        }
        __syncthreads();

        // ---- compute: one m16n8k16 x 3 terms per (i,j) ----
        {
            uint2 af[2][4];
#pragma unroll
            for (int i = 0; i < 2; ++i) {
                int r = wm + i * 16 + group;
                af[i][0] = As[r][tig];
                af[i][1] = As[r + 8][tig];
                af[i][2] = As[r][tig + 4];
                af[i][3] = As[r + 8][tig + 4];
            }
            uint2 bf[8][2];
#pragma unroll
            for (int j = 0; j < 8; ++j) {
                int nc_ = wn + j * 8 + group;
                bf[j][0] = Bs[tig][nc_];
                bf[j][1] = Bs[tig + 4][nc_];
            }
#pragma unroll
            for (int i = 0; i < 2; ++i)
#pragma unroll
                for (int j = 0; j < 8; ++j) {
                    // hi * hi
                    asm volatile(
                        "mma.sync.aligned.m16n8k16.row.col.f32.bf16.bf16.f32 "
                        "{%0,%1,%2,%3},{%4,%5,%6,%7},{%8,%9},{%0,%1,%2,%3};"
                        : "+f"(c[i][j][0]), "+f"(c[i][j][1]),
                          "+f"(c[i][j][2]), "+f"(c[i][j][3])
                        : "r"(af[i][0].x), "r"(af[i][1].x), "r"(af[i][2].x), "r"(af[i][3].x),
                          "r"(bf[j][0].x), "r"(bf[j][1].x));
                    // lo * hi
                    asm volatile(
                        "mma.sync.aligned.m16n8k16.row.col.f32.bf16.bf16.f32 "
                        "{%0,%1,%2,%3},{%4,%5,%6,%7},{%8,%9},{%0,%1,%2,%3};"
                        : "+f"(c[i][j][0]), "+f"(c[i][j][1]),
                          "+f"(c[i][j][2]), "+f"(c[i][j][3])
                        : "r"(af[i][0].y), "r"(af[i][1].y), "r"(af[i][2].y), "r"(af[i][3].y),
                          "r"(bf[j][0].x), "r"(bf[j][1].x));
                    // hi * lo
                    asm volatile(
                        "mma.sync.aligned.m16n8k16.row.col.f32.bf16.bf16.f32 "
                        "{%0,%1,%2,%3},{%4,%5,%6,%7},{%8,%9},{%0,%1,%2,%3};"
                        : "+f"(c[i][j][0]), "+f"(c[i][j][1]),
                          "+f"(c[i][j][2]), "+f"(c[i][j][3])
                        : "r"(af[i][0].x), "r"(af[i][1].x), "r"(af[i][2].x), "r"(af[i][3].x),
                          "r"(bf[j][0].y), "r"(bf[j][1].y));
                }
        }
        __syncthreads();
    }

    // ---- epilogue ----
#pragma unroll
    for (int i = 0; i < 2; ++i) {
        int r0 = bm + wm + i * 16 + group;
#pragma unroll
        for (int j = 0; j < 8; ++j) {
            int col = bn + wn + j * 8 + tig * 2;
            float bb0 = bias[col], bb1 = bias[col + 1];
            if (DUAL) { bb0 += bias2[col]; bb1 += bias2[col + 1]; }
            if (r0 < M) {
                float v0 = c[i][j][0] + bb0, v1 = c[i][j][1] + bb1;
                if (RELU) { v0 = fmaxf(v0, 0.f); v1 = fmaxf(v1, 0.f); }
                C[(size_t)r0 * Nc + col] = v0;
                C[(size_t)r0 * Nc + col + 1] = v1;
            }
            if (r0 + 8 < M) {
                float v2 = c[i][j][2] + bb0, v3 = c[i][j][3] + bb1;
                if (RELU) { v2 = fmaxf(v2, 0.f); v3 = fmaxf(v3, 0.f); }
                C[(size_t)(r0 + 8) * Nc + col] = v2;
                C[(size_t)(r0 + 8) * Nc + col + 1] = v3;
            }
        }
    }
}

// ---------------- CSR build --------------------------------------------------
__global__ __launch_bounds__(256) void count_kernel(const int* __restrict__ dst,
                                                    int* __restrict__ cnt)
{
    int e = blockIdx.x * blockDim.x + threadIdx.x;
    if (e < EE) atomicAdd(&cnt[dst[e]], 1);
}

__global__ __launch_bounds__(1024) void scan_kernel(const int* __restrict__ cnt,
                                                    int* __restrict__ off,
                                                    int* __restrict__ cur)
{
    __shared__ int sh[1024];
    __shared__ int carry;
    int t = threadIdx.x;
    if (t == 0) carry = 0;
    __syncthreads();
    for (int base = 0; base < NN; base += 1024) {
        int i = base + t;
        int v = (i < NN) ? cnt[i] : 0;
        sh[t] = v;
        __syncthreads();
        for (int o = 1; o < 1024; o <<= 1) {
            int x = (t >= o) ? sh[t - o] : 0;
            __syncthreads();
            sh[t] += x;
            __syncthreads();
        }
        int excl = sh[t] - v;
        if (i < NN) { off[i] = carry + excl; cur[i] = carry + excl; }
        __syncthreads();
        if (t == 0) carry += sh[1023];
        __syncthreads();
    }
    if (t == 0) off[NN] = carry;
}

__global__ __launch_bounds__(256) void fill_kernel(const int* __restrict__ src,
                                                   const int* __restrict__ dst,
                                                   int* __restrict__ cur,
                                                   int* __restrict__ csr)
{
    int e = blockIdx.x * blockDim.x + threadIdx.x;
    if (e < EE) {
        int d = dst[e];
        int pos = atomicAdd(&cur[d], 1);
        csr[pos] = src[e];
    }
}

// ---------------- neighbor mean (warp per node, CSR gather) ------------------
__global__ __launch_bounds__(256) void agg_kernel(
    const int* __restrict__ off, const int* __restrict__ csr,
    const float* __restrict__ h, float* __restrict__ mean)
{
    int n = blockIdx.x * 8 + (threadIdx.x >> 5);
    if (n >= NN) return;
    int lane = threadIdx.x & 31;
    int s0 = off[n], s1 = off[n + 1];
    float4 a0 = make_float4(0.f, 0.f, 0.f, 0.f), a1 = a0;
    for (int e = s0; e < s1; ++e) {
        int s = csr[e];
        const float4* hp = (const float4*)(h + (size_t)s * HD);
        float4 v0 = hp[lane], v1 = hp[lane + 32];
        a0.x += v0.x; a0.y += v0.y; a0.z += v0.z; a0.w += v0.w;
        a1.x += v1.x; a1.y += v1.y; a1.z += v1.z; a1.w += v1.w;
    }
    float inv = 1.f / (float)max(s1 - s0, 1);
    a0.x *= inv; a0.y *= inv; a0.z *= inv; a0.w *= inv;
    a1.x *= inv; a1.y *= inv; a1.z *= inv; a1.w *= inv;
    float4* mp = (float4*)(mean + (size_t)n * HD);
    mp[lane] = a0;
    mp[lane + 32] = a1;
}

// ---------------- fused ReLU + LayerNorm (warp per row, H=256) ---------------
__global__ __launch_bounds__(256) void relu_ln_kernel(
    const float* __restrict__ X, float* __restrict__ Y,
    const float* __restrict__ gamma, const float* __restrict__ beta, int M)
{
    int row = blockIdx.x * 8 + (threadIdx.x >> 5);
    if (row >= M) return;
    int lane = threadIdx.x & 31;
    const float* x = X + (size_t)row * HD;
    float v[8];
    float s = 0.f;
#pragma unroll
    for (int i = 0; i < 8; ++i) { v[i] = fmaxf(x[lane + 32 * i], 0.f); s += v[i]; }
#pragma unroll
    for (int o = 16; o; o >>= 1) s += __shfl_xor_sync(0xffffffffu, s, o);
    float mu = s * (1.f / HD);
    float q = 0.f;
#pragma unroll
    for (int i = 0; i < 8; ++i) { float d = v[i] - mu; q += d * d; }
#pragma unroll
    for (int o = 16; o; o >>= 1) q += __shfl_xor_sync(0xffffffffu, q, o);
    float rstd = rsqrtf(q * (1.f / HD) + 1e-5f);
    float* y = Y + (size_t)row * HD;
#pragma unroll
    for (int i = 0; i < 8; ++i) {
        int c = lane + 32 * i;
        y[c] = (v[i] - mu) * rstd * gamma[c] + beta[c];
    }
}

// ---------------- L2 row-normalize ------------------------------------------
__global__ __launch_bounds__(256) void l2norm_kernel(
    const float* __restrict__ X, float* __restrict__ Y, int M)
{
    int row = blockIdx.x * 8 + (threadIdx.x >> 5);
    if (row >= M) return;
    int lane = threadIdx.x & 31;
    const float* x = X + (size_t)row * HD;
    float v[8];
    float s = 0.f;
#pragma unroll
    for (int i = 0; i < 8; ++i) { v[i] = x[lane + 32 * i]; s += v[i] * v[i]; }
#pragma unroll
    for (int o = 16; o; o >>= 1) s += __shfl_xor_sync(0xffffffffu, s, o);
    float sc = 1.f / fmaxf(sqrtf(s), 1e-12f);
    float* y = Y + (size_t)row * HD;
#pragma unroll
    for (int i = 0; i < 8; ++i) y[lane + 32 * i] = v[i] * sc;
}

// ---------------- final logits ----------------------------------------------
__global__ __launch_bounds__(256) void logits_kernel(
    const float* __restrict__ z2, const float* __restrict__ W3,
    const float* __restrict__ b3, float* __restrict__ out)
{
    int p = blockIdx.x * 8 + (threadIdx.x >> 5);
    if (p >= PP) return;
    int lane = threadIdx.x & 31;
    const float* z = z2 + (size_t)p * HIDD;
    float s = 0.f;
#pragma unroll
    for (int i = 0; i < 4; ++i) { int c = lane + 32 * i; s += z[c] * W3[c]; }
#pragma unroll
    for (int o = 16; o; o >>= 1) s += __shfl_xor_sync(0xffffffffu, s, o);
    if (lane == 0) out[p] = s + b3[0];
}

// ---------------- launch ----------------------------------------------------
extern "C" void kernel_launch(void* const* d_in, const int* in_sizes, int n_in,
                              void* d_out, int out_size)
{
    const float* X       = (const float*)d_in[0];
    const int*   edge    = (const int*)d_in[1];
    const int*   i_idx   = (const int*)d_in[2];
    const int*   j_idx   = (const int*)d_in[3];
    const float* W_in    = (const float*)d_in[4];
    const float* b_in    = (const float*)d_in[5];
    const float* Ws_self = (const float*)d_in[6];
    const float* bs_self = (const float*)d_in[7];
    const float* Ws_nei  = (const float*)d_in[8];
    const float* bs_nei  = (const float*)d_in[9];
    const float* gammas  = (const float*)d_in[10];
    const float* betas   = (const float*)d_in[11];
    const float* W1      = (const float*)d_in[12];
    const float* b1      = (const float*)d_in[13];
    const float* W2      = (const float*)d_in[14];
    const float* b2      = (const float*)d_in[15];
    const float* W3      = (const float*)d_in[16];
    const float* b3      = (const float*)d_in[17];

    const int* src = edge;
    const int* dst = edge + EE;

    float *h, *tmp, *mean, *z1, *z2;
    int *cnt, *off, *cur, *csr;
    cudaGetSymbolAddress((void**)&h,    g_h);
    cudaGetSymbolAddress((void**)&tmp,  g_tmp);
    cudaGetSymbolAddress((void**)&mean, g_mean);
    cudaGetSymbolAddress((void**)&z1,   g_z1);
    cudaGetSymbolAddress((void**)&z2,   g_z2);
    cudaGetSymbolAddress((void**)&cnt,  g_cnt);
    cudaGetSymbolAddress((void**)&off,  g_off);
    cudaGetSymbolAddress((void**)&cur,  g_cur);
    cudaGetSymbolAddress((void**)&csr,  g_csr);

    float* outH = (float*)d_out;
    float* outL = outH + (size_t)NN * HD;

    dim3 blk(256);

    // 1) encoder: h = relu(X @ W_in + b_in)
    mma_gemm<true, false, false><<<dim3(HD / 128, (NN + 127) / 128), blk>>>(
        X, W_in, b_in, nullptr, nullptr, nullptr, nullptr, nullptr,
        h, NN, HD, IND);

    // 2) CSR build
    cudaMemsetAsync(cnt, 0, NN * sizeof(int));
    count_kernel<<<(EE + 255) / 256, blk>>>(dst, cnt);
    scan_kernel<<<1, 1024>>>(cnt, off, cur);
    fill_kernel<<<(EE + 255) / 256, blk>>>(src, dst, cur, csr);

    // 3) GNN layers
    for (int l = 0; l < 3; ++l) {
        agg_kernel<<<(NN + 7) / 8, blk>>>(off, csr, h, mean);
        mma_gemm<false, true, false><<<dim3(HD / 128, (NN + 127) / 128), blk>>>(
            h, Ws_self + (size_t)l * HD * HD, bs_self + (size_t)l * HD,
            mean, Ws_nei + (size_t)l * HD * HD, bs_nei + (size_t)l * HD,
            nullptr, nullptr, tmp, NN, HD, HD);
        relu_ln_kernel<<<(NN + 7) / 8, blk>>>(tmp, h, gammas + (size_t)l * HD,
                                              betas + (size_t)l * HD, NN);
    }

    // 4) H = l2-normalize(h)
    l2norm_kernel<<<(NN + 7) / 8, blk>>>(h, outH, NN);

    // 5) edge head (feat fused into GEMM1 A-loader)
    mma_gemm<true, false, true><<<dim3(HIDD / 128, (PP + 127) / 128), blk>>>(
        outH, W1, b1, nullptr, nullptr, nullptr, i_idx, j_idx,
        z1, PP, HIDD, 2 * HD);
    mma_gemm<true, false, false><<<dim3(HIDD / 128, (PP + 127) / 128), blk>>>(
        z1, W2, b2, nullptr, nullptr, nullptr, nullptr, nullptr,
        z2, PP, HIDD, HIDD);
    logits_kernel<<<(PP + 7) / 8, blk>>>(z2, W3, b3, outL);
}

// round 16
// speedup vs baseline: 2.1318x; 1.1451x over previous
#include <cuda_runtime.h>

#define NN   50000
#define EE   300000
#define PP   200000
#define IND  480
#define HD   256
#define HIDD 128

// ---------------- scratch (device globals) ----------------------------------
__device__ float g_h[(size_t)NN * HD];
__device__ float g_tmp[(size_t)NN * HD];
__device__ float g_mean[(size_t)NN * HD];
__device__ float g_z1[(size_t)PP * HIDD];
__device__ float g_z2[(size_t)PP * HIDD];
__device__ int   g_cnt[NN];
__device__ int   g_off[NN + 1];
__device__ int   g_cur[NN];
__device__ int   g_csr[EE];

// ---------------- helpers ----------------------------------------------------
__device__ __forceinline__ unsigned smem_u32(const void* p) {
    unsigned r;
    asm("{ .reg .u64 t; cvta.to.shared.u64 t, %1; cvt.u32.u64 %0, t; }"
        : "=r"(r) : "l"(p));
    return r;
}

// pack two fp32 into (bf16x2 hi-pair, bf16x2 lo-pair); low half = x0
__device__ __forceinline__ uint2 bsplit2(float x0, float x1) {
    unsigned hp;
    asm("cvt.rn.bf16x2.f32 %0, %1, %2;" : "=r"(hp) : "f"(x1), "f"(x0));
    float h0 = __uint_as_float(hp << 16);
    float h1 = __uint_as_float(hp & 0xffff0000u);
    unsigned lp;
    asm("cvt.rn.bf16x2.f32 %0, %1, %2;" : "=r"(lp) : "f"(x1 - h1), "f"(x0 - h0));
    return make_uint2(hp, lp);
}

#define SWZ128(off) ((off) ^ (((off) >> 3) & 0x70))

// tcgen05 smem layout (dynamic smem)
#define OFF_TMEM 0
#define OFF_MBAR 8
#define OFF_AHI  1024
#define OFF_ALO  (OFF_AHI + 16384)
#define OFF_BHI  (OFF_ALO + 16384)
#define OFF_BLO  (OFF_BHI + 16384)
#define SMEM_TOT (OFF_BLO + 16384 + 64)

#if defined(__CUDA_ARCH__) && defined(__CUDA_ARCH_FEAT_SM103_ALL)
#define HAS_TCGEN05 1
#else
#define HAS_TCGEN05 0
#endif

#if HAS_TCGEN05
__device__ __forceinline__ unsigned elect1() {
    unsigned p;
    asm volatile("{\n\t.reg .pred p;\n\telect.sync _|p, 0xFFFFFFFF;\n\t"
                 "selp.b32 %0, 1, 0, p;\n\t}" : "=r"(p));
    return p;
}
__device__ __forceinline__ unsigned long long mk_desc(unsigned addr) {
    const unsigned long long base =
        (2ull << 61) | (1ull << 46) | (64ull << 32) | (1ull << 16);
    return base | ((unsigned long long)(addr >> 4) & 0x3FFFull);
}
__device__ __forceinline__ void mma_f16_ss(unsigned d, unsigned long long ad,
                                           unsigned long long bd, unsigned idesc,
                                           unsigned en) {
    asm volatile(
        "{\n\t.reg .pred p;\n\tsetp.ne.u32 p, %5, 0;\n\t"
        "tcgen05.mma.cta_group::1.kind::f16 [%0], %1, %2, %3, {%4,%4,%4,%4}, p;\n\t}"
        :: "r"(d), "l"(ad), "l"(bd), "r"(idesc), "r"(0u), "r"(en) : "memory");
}
__device__ __forceinline__ void mbar_wait(unsigned mbar, unsigned parity) {
    asm volatile(
        "{\n\t.reg .pred P;\n\tW%=:\n\t"
        "mbarrier.try_wait.parity.acquire.cta.shared::cta.b64 P, [%0], %1, 0x989680;\n\t"
        "@!P bra W%=;\n\t}" :: "r"(mbar), "r"(parity) : "memory");
}
#endif

// ---------------- GEMM: tcgen05 (sm_103a) or mma.sync fallback --------------
// C[M,Nc] = act( A@B + bias (+ A2@B2 + bias2 if DUAL) )
// FEAT: logical A row p = concat(|H[i]-H[j]|, H[i]*H[j]), K = 2*HD.
template <bool RELU, bool DUAL, bool FEAT>
__global__ __launch_bounds__(256) void tc_gemm(
    const float* __restrict__ A, const float* __restrict__ B,
    const float* __restrict__ bias,
    const float* __restrict__ A2, const float* __restrict__ B2,
    const float* __restrict__ bias2,
    const int* __restrict__ iidx, const int* __restrict__ jidx,
    float* __restrict__ C, int M, int Nc, int K)
{
#if HAS_TCGEN05
    // ================= tcgen05 path: 128x128 tile, SS bf16 3-term ===========
    extern __shared__ char smem[];
    const unsigned sb = smem_u32(smem);
    const int tid = threadIdx.x;
    const int warp = tid >> 5, lane = tid & 31;
    const int bm = blockIdx.y * 128, bn = blockIdx.x * 128;

    const unsigned IDESC = (1u << 4) | (1u << 7) | (1u << 10) |
                           ((128u / 8) << 17) | ((128u / 16) << 24);

    if (warp == 4) {
        asm volatile(
            "tcgen05.alloc.cta_group::1.sync.aligned.shared::cta.b32 [%0], %1;"
            :: "r"(sb + OFF_TMEM), "r"(128u) : "memory");
    }
    if (tid == 0) {
        asm volatile("mbarrier.init.shared.b64 [%0], %1;"
                     :: "r"(sb + OFF_MBAR), "r"(1u) : "memory");
    }
    __syncthreads();
    unsigned tmem;
    asm volatile("ld.shared.b32 %0, [%1];" : "=r"(tmem) : "r"(sb + OFF_TMEM));

    const int nCh = (K + 63) >> 6;
    const int nIter = (DUAL ? 2 : 1) * nCh;

    const int am = tid >> 1, ah = (tid & 1) * 32;
    const int arow = bm + am;
    int ia = 0, jb = 0;
    if (FEAT && arow < M) { ia = iidx[arow]; jb = jidx[arow]; }
    const int bnn = tid & 127, bkh = (tid >> 7) * 32;

    for (int it = 0; it < nIter; ++it) {
        const int part = DUAL ? (it / nCh) : 0;
        const int k0 = (it - part * nCh) * 64;
        const float* Ap = (DUAL && part) ? A2 : A;
        const float* Bp = (DUAL && part) ? B2 : B;

        float a[32];
        {
            const bool valid = (arow < M) && (k0 + ah < K);
            if (valid) {
                if (FEAT) {
                    const float* Ha = A + (size_t)ia * HD;
                    const float* Hb = A + (size_t)jb * HD;
#pragma unroll
                    for (int q = 0; q < 8; ++q) {
                        int kg = k0 + ah + q * 4;
                        float4 xa, xb, r;
                        if (kg < HD) {
                            xa = *(const float4*)(Ha + kg);
                            xb = *(const float4*)(Hb + kg);
                            r = make_float4(fabsf(xa.x - xb.x), fabsf(xa.y - xb.y),
                                            fabsf(xa.z - xb.z), fabsf(xa.w - xb.w));
                        } else {
                            xa = *(const float4*)(Ha + kg - HD);
                            xb = *(const float4*)(Hb + kg - HD);
                            r = make_float4(xa.x * xb.x, xa.y * xb.y,
                                            xa.z * xb.z, xa.w * xb.w);
                        }
                        a[q * 4 + 0] = r.x; a[q * 4 + 1] = r.y;
                        a[q * 4 + 2] = r.z; a[q * 4 + 3] = r.w;
                    }
                } else {
                    const float* p = Ap + (size_t)arow * K + k0 + ah;
#pragma unroll
                    for (int q = 0; q < 8; ++q) {
                        float4 v = *(const float4*)(p + q * 4);
                        a[q * 4 + 0] = v.x; a[q * 4 + 1] = v.y;
                        a[q * 4 + 2] = v.z; a[q * 4 + 3] = v.w;
                    }
                }
            } else {
#pragma unroll
                for (int q = 0; q < 32; ++q) a[q] = 0.f;
            }
        }
        float b[32];
        {
            const bool valid = (k0 + bkh < K);
            if (valid) {
                const float* p = Bp + (size_t)(k0 + bkh) * Nc + bn + bnn;
#pragma unroll
                for (int q = 0; q < 32; ++q) b[q] = p[(size_t)q * Nc];
            } else {
#pragma unroll
                for (int q = 0; q < 32; ++q) b[q] = 0.f;
            }
        }

        if (it > 0) mbar_wait(sb + OFF_MBAR, (it - 1) & 1);

#pragma unroll
        for (int g = 0; g < 4; ++g) {
            uint2 p0 = bsplit2(a[g * 8 + 0], a[g * 8 + 1]);
            uint2 p1 = bsplit2(a[g * 8 + 2], a[g * 8 + 3]);
            uint2 p2 = bsplit2(a[g * 8 + 4], a[g * 8 + 5]);
            uint2 p3 = bsplit2(a[g * 8 + 6], a[g * 8 + 7]);
            unsigned off = (unsigned)(am * 128 + (ah + g * 8) * 2);
            unsigned sw = SWZ128(off);
            *(uint4*)(smem + OFF_AHI + sw) = make_uint4(p0.x, p1.x, p2.x, p3.x);
            *(uint4*)(smem + OFF_ALO + sw) = make_uint4(p0.y, p1.y, p2.y, p3.y);
        }
#pragma unroll
        for (int g = 0; g < 4; ++g) {
            uint2 p0 = bsplit2(b[g * 8 + 0], b[g * 8 + 1]);
            uint2 p1 = bsplit2(b[g * 8 + 2], b[g * 8 + 3]);
            uint2 p2 = bsplit2(b[g * 8 + 4], b[g * 8 + 5]);
            uint2 p3 = bsplit2(b[g * 8 + 6], b[g * 8 + 7]);
            unsigned off = (unsigned)(bnn * 128 + (bkh + g * 8) * 2);
            unsigned sw = SWZ128(off);
            *(uint4*)(smem + OFF_BHI + sw) = make_uint4(p0.x, p1.x, p2.x, p3.x);
            *(uint4*)(smem + OFF_BLO + sw) = make_uint4(p0.y, p1.y, p2.y, p3.y);
        }
        asm volatile("fence.proxy.async.shared::cta;" ::: "memory");
        __syncthreads();

        if (warp == 4) {
            if (elect1()) {
                unsigned long long dAh = mk_desc(sb + OFF_AHI);
                unsigned long long dAl = mk_desc(sb + OFF_ALO);
                unsigned long long dBh = mk_desc(sb + OFF_BHI);
                unsigned long long dBl = mk_desc(sb + OFF_BLO);
#pragma unroll
                for (int ks = 0; ks < 4; ++ks) {
                    unsigned en0 = (it > 0 || ks > 0) ? 1u : 0u;
                    mma_f16_ss(tmem, dAh + ks * 2, dBh + ks * 2, IDESC, en0);
                    mma_f16_ss(tmem, dAl + ks * 2, dBh + ks * 2, IDESC, 1u);
                    mma_f16_ss(tmem, dAh + ks * 2, dBl + ks * 2, IDESC, 1u);
                }
                asm volatile(
                    "tcgen05.commit.cta_group::1.mbarrier::arrive::one.shared::cluster.b64 [%0];"
                    :: "r"(sb + OFF_MBAR) : "memory");
            }
        }
    }

    mbar_wait(sb + OFF_MBAR, (nIter - 1) & 1);
    asm volatile("tcgen05.fence::after_thread_sync;" ::: "memory");

    if (warp < 4) {
        int m = bm + warp * 32 + lane;
#pragma unroll
        for (int half = 0; half < 2; ++half) {
            unsigned d[64];
            asm volatile(
                "tcgen05.ld.sync.aligned.32x32b.x32.b32 "
                "{%0,%1,%2,%3,%4,%5,%6,%7,%8,%9,%10,%11,%12,%13,%14,%15,"
                "%16,%17,%18,%19,%20,%21,%22,%23,%24,%25,%26,%27,%28,%29,%30,%31}, [%32];"
                : "=r"(d[0]), "=r"(d[1]), "=r"(d[2]), "=r"(d[3]), "=r"(d[4]),
                  "=r"(d[5]), "=r"(d[6]), "=r"(d[7]), "=r"(d[8]), "=r"(d[9]),
                  "=r"(d[10]), "=r"(d[11]), "=r"(d[12]), "=r"(d[13]), "=r"(d[14]),
                  "=r"(d[15]), "=r"(d[16]), "=r"(d[17]), "=r"(d[18]), "=r"(d[19]),
                  "=r"(d[20]), "=r"(d[21]), "=r"(d[22]), "=r"(d[23]), "=r"(d[24]),
                  "=r"(d[25]), "=r"(d[26]), "=r"(d[27]), "=r"(d[28]), "=r"(d[29]),
                  "=r"(d[30]), "=r"(d[31])
                : "r"(tmem + half * 64));
            asm volatile(
                "tcgen05.ld.sync.aligned.32x32b.x32.b32 "
                "{%0,%1,%2,%3,%4,%5,%6,%7,%8,%9,%10,%11,%12,%13,%14,%15,"
                "%16,%17,%18,%19,%20,%21,%22,%23,%24,%25,%26,%27,%28,%29,%30,%31}, [%32];"
                : "=r"(d[32]), "=r"(d[33]), "=r"(d[34]), "=r"(d[35]), "=r"(d[36]),
                  "=r"(d[37]), "=r"(d[38]), "=r"(d[39]), "=r"(d[40]), "=r"(d[41]),
                  "=r"(d[42]), "=r"(d[43]), "=r"(d[44]), "=r"(d[45]), "=r"(d[46]),
                  "=r"(d[47]), "=r"(d[48]), "=r"(d[49]), "=r"(d[50]), "=r"(d[51]),
                  "=r"(d[52]), "=r"(d[53]), "=r"(d[54]), "=r"(d[55]), "=r"(d[56]),
                  "=r"(d[57]), "=r"(d[58]), "=r"(d[59]), "=r"(d[60]), "=r"(d[61]),
                  "=r"(d[62]), "=r"(d[63])
                : "r"(tmem + half * 64 + 32));
            asm volatile("tcgen05.wait::ld.sync.aligned;" ::: "memory");
            if (m < M) {
#pragma unroll
                for (int c4 = 0; c4 < 16; ++c4) {
                    int col = bn + half * 64 + c4 * 4;
                    float v0 = __uint_as_float(d[c4 * 4 + 0]) + bias[col + 0];
                    float v1 = __uint_as_float(d[c4 * 4 + 1]) + bias[col + 1];
                    float v2 = __uint_as_float(d[c4 * 4 + 2]) + bias[col + 2];
                    float v3 = __uint_as_float(d[c4 * 4 + 3]) + bias[col + 3];
                    if (DUAL) {
                        v0 += bias2[col + 0]; v1 += bias2[col + 1];
                        v2 += bias2[col + 2]; v3 += bias2[col + 3];
                    }
                    if (RELU) {
                        v0 = fmaxf(v0, 0.f); v1 = fmaxf(v1, 0.f);
                        v2 = fmaxf(v2, 0.f); v3 = fmaxf(v3, 0.f);
                    }
                    *(float4*)(C + (size_t)m * Nc + col) = make_float4(v0, v1, v2, v3);
                }
            }
        }
    }
    __syncthreads();
    if (tid == 0) {
        asm volatile("mbarrier.inval.shared.b64 [%0];"
                     :: "r"(sb + OFF_MBAR) : "memory");
    }
    if (warp == 4) {
        asm volatile("tcgen05.dealloc.cta_group::1.sync.aligned.b32 %0, %1;"
                     :: "r"(tmem), "r"(128u));
    }
#else
    // ================= fallback: proven mma.sync bf16 3-term (round 10) =====
    constexpr int PA = 12;
    constexpr int PB = 132;
    __shared__ uint2 As[128][PA];
    __shared__ uint2 Bs[8][PB];

    const int tid  = threadIdx.x;
    const int warp = tid >> 5, lane = tid & 31;
    const int group = lane >> 2, tig = lane & 3;
    const int wm = (warp & 3) * 32, wn = (warp >> 2) * 64;
    const int bm = blockIdx.y * 128, bn = blockIdx.x * 128;

    const int kIters = K / 16;
    const int nIter = (DUAL ? 2 : 1) * kIters;

    const int am = tid >> 1, akq = (tid & 1) * 8;
    const int arow = bm + am;
    int ia = 0, jb = 0;
    if (FEAT && arow < M) { ia = iidx[arow]; jb = jidx[arow]; }
    const int bkp = tid >> 5;
    const int bc0 = (tid & 31) * 4;

    float c[2][8][4] = {};

    for (int it = 0; it < nIter; ++it) {
        const int part = DUAL ? (it / kIters) : 0;
        const int k0 = (it - part * kIters) * 16;

        {
            float ra[8];
#pragma unroll
            for (int q = 0; q < 8; ++q) ra[q] = 0.f;
            if (arow < M) {
                if (FEAT) {
                    const float* Ha = A + (size_t)ia * HD;
                    const float* Hb = A + (size_t)jb * HD;
                    int k = k0 + akq;
#pragma unroll
                    for (int q = 0; q < 2; ++q) {
                        int kk = k + q * 4;
                        float4 r;
                        if (kk < HD) {
                            float4 xa = *(const float4*)(Ha + kk);
                            float4 xb = *(const float4*)(Hb + kk);
                            r = make_float4(fabsf(xa.x - xb.x), fabsf(xa.y - xb.y),
                                            fabsf(xa.z - xb.z), fabsf(xa.w - xb.w));
                        } else {
                            float4 xa = *(const float4*)(Ha + kk - HD);
                            float4 xb = *(const float4*)(Hb + kk - HD);
                            r = make_float4(xa.x * xb.x, xa.y * xb.y,
                                            xa.z * xb.z, xa.w * xb.w);
                        }
                        ra[q * 4 + 0] = r.x; ra[q * 4 + 1] = r.y;
                        ra[q * 4 + 2] = r.z; ra[q * 4 + 3] = r.w;
                    }
                } else {
                    const float* Ap = (DUAL && part) ? A2 : A;
                    const float* p = Ap + (size_t)arow * K + k0 + akq;
                    float4 v0 = *(const float4*)p;
                    float4 v1 = *(const float4*)(p + 4);
                    ra[0] = v0.x; ra[1] = v0.y; ra[2] = v0.z; ra[3] = v0.w;
                    ra[4] = v1.x; ra[5] = v1.y; ra[6] = v1.z; ra[7] = v1.w;
                }
            }
            uint2 s0 = bsplit2(ra[0], ra[1]);
            uint2 s1 = bsplit2(ra[2], ra[3]);
            uint2 s2 = bsplit2(ra[4], ra[5]);
            uint2 s3 = bsplit2(ra[6], ra[7]);
            uint4* dp = (uint4*)&As[am][(tid & 1) * 4];
            dp[0] = make_uint4(s0.x, s0.y, s1.x, s1.y);
            dp[1] = make_uint4(s2.x, s2.y, s3.x, s3.y);
        }
        {
            const float* Bp = (DUAL && part) ? B2 : B;
            const float* p0 = Bp + (size_t)(k0 + 2 * bkp) * Nc + bn + bc0;
            const float* p1 = p0 + Nc;
            float4 r0 = *(const float4*)p0;
            float4 r1 = *(const float4*)p1;
            uint2 s0 = bsplit2(r0.x, r1.x);
            uint2 s1 = bsplit2(r0.y, r1.y);
            uint2 s2 = bsplit2(r0.z, r1.z);
            uint2 s3 = bsplit2(r0.w, r1.w);
            uint4* dp = (uint4*)&Bs[bkp][bc0];
            dp[0] = make_uint4(s0.x, s0.y, s1.x, s1.y);
            dp[1] = make_uint4(s2.x, s2.y, s3.x, s3.y);
        }
        __syncthreads();

        {
            uint2 af[2][4];
#pragma unroll
            for (int i = 0; i < 2; ++i) {
                int r = wm + i * 16 + group;
                af[i][0] = As[r][tig];
                af[i][1] = As[r + 8][tig];
                af[i][2] = As[r][tig + 4];
                af[i][3] = As[r + 8][tig + 4];
            }
            uint2 bf[8][2];
#pragma unroll
            for (int j = 0; j < 8; ++j) {
                int nc_ = wn + j * 8 + group;
                bf[j][0] = Bs[tig][nc_];
                bf[j][1] = Bs[tig + 4][nc_];
            }
#pragma unroll
            for (int i = 0; i < 2; ++i)
#pragma unroll
                for (int j = 0; j < 8; ++j) {
                    asm volatile(
                        "mma.sync.aligned.m16n8k16.row.col.f32.bf16.bf16.f32 "
                        "{%0,%1,%2,%3},{%4,%5,%6,%7},{%8,%9},{%0,%1,%2,%3};"
                        : "+f"(c[i][j][0]), "+f"(c[i][j][1]),
                          "+f"(c[i][j][2]), "+f"(c[i][j][3])
                        : "r"(af[i][0].x), "r"(af[i][1].x), "r"(af[i][2].x), "r"(af[i][3].x),
                          "r"(bf[j][0].x), "r"(bf[j][1].x));
                    asm volatile(
                        "mma.sync.aligned.m16n8k16.row.col.f32.bf16.bf16.f32 "
                        "{%0,%1,%2,%3},{%4,%5,%6,%7},{%8,%9},{%0,%1,%2,%3};"
                        : "+f"(c[i][j][0]), "+f"(c[i][j][1]),
                          "+f"(c[i][j][2]), "+f"(c[i][j][3])
                        : "r"(af[i][0].y), "r"(af[i][1].y), "r"(af[i][2].y), "r"(af[i][3].y),
                          "r"(bf[j][0].x), "r"(bf[j][1].x));
                    asm volatile(
                        "mma.sync.aligned.m16n8k16.row.col.f32.bf16.bf16.f32 "
                        "{%0,%1,%2,%3},{%4,%5,%6,%7},{%8,%9},{%0,%1,%2,%3};"
                        : "+f"(c[i][j][0]), "+f"(c[i][j][1]),
                          "+f"(c[i][j][2]), "+f"(c[i][j][3])
                        : "r"(af[i][0].x), "r"(af[i][1].x), "r"(af[i][2].x), "r"(af[i][3].x),
                          "r"(bf[j][0].y), "r"(bf[j][1].y));
                }
        }
        __syncthreads();
    }

#pragma unroll
    for (int i = 0; i < 2; ++i) {
        int r0 = bm + wm + i * 16 + group;
#pragma unroll
        for (int j = 0; j < 8; ++j) {
            int col = bn + wn + j * 8 + tig * 2;
            float bb0 = bias[col], bb1 = bias[col + 1];
            if (DUAL) { bb0 += bias2[col]; bb1 += bias2[col + 1]; }
            if (r0 < M) {
                float v0 = c[i][j][0] + bb0, v1 = c[i][j][1] + bb1;
                if (RELU) { v0 = fmaxf(v0, 0.f); v1 = fmaxf(v1, 0.f); }
                C[(size_t)r0 * Nc + col] = v0;
                C[(size_t)r0 * Nc + col + 1] = v1;
            }
            if (r0 + 8 < M) {
                float v2 = c[i][j][2] + bb0, v3 = c[i][j][3] + bb1;
                if (RELU) { v2 = fmaxf(v2, 0.f); v3 = fmaxf(v3, 0.f); }
                C[(size_t)(r0 + 8) * Nc + col] = v2;
                C[(size_t)(r0 + 8) * Nc + col + 1] = v3;
            }
        }
    }
#endif
}

// ---------------- CSR build --------------------------------------------------
__global__ __launch_bounds__(256) void count_kernel(const int* __restrict__ dst,
                                                    int* __restrict__ cnt)
{
    int e = blockIdx.x * blockDim.x + threadIdx.x;
    if (e < EE) atomicAdd(&cnt[dst[e]], 1);
}

__global__ __launch_bounds__(1024) void scan_kernel(const int* __restrict__ cnt,
                                                    int* __restrict__ off,
                                                    int* __restrict__ cur)
{
    __shared__ int sh[1024];
    __shared__ int carry;
    int t = threadIdx.x;
    if (t == 0) carry = 0;
    __syncthreads();
    for (int base = 0; base < NN; base += 1024) {
        int i = base + t;
        int v = (i < NN) ? cnt[i] : 0;
        sh[t] = v;
        __syncthreads();
        for (int o = 1; o < 1024; o <<= 1) {
            int x = (t >= o) ? sh[t - o] : 0;
            __syncthreads();
            sh[t] += x;
            __syncthreads();
        }
        int excl = sh[t] - v;
        if (i < NN) { off[i] = carry + excl; cur[i] = carry + excl; }
        __syncthreads();
        if (t == 0) carry += sh[1023];
        __syncthreads();
    }
    if (t == 0) off[NN] = carry;
}

__global__ __launch_bounds__(256) void fill_kernel(const int* __restrict__ src,
                                                   const int* __restrict__ dst,
                                                   int* __restrict__ cur,
                                                   int* __restrict__ csr)
{
    int e = blockIdx.x * blockDim.x + threadIdx.x;
    if (e < EE) {
        int d = dst[e];
        int pos = atomicAdd(&cur[d], 1);
        csr[pos] = src[e];
    }
}

// ---------------- neighbor mean (warp per node, CSR gather) ------------------
__global__ __launch_bounds__(256) void agg_kernel(
    const int* __restrict__ off, const int* __restrict__ csr,
    const float* __restrict__ h, float* __restrict__ mean)
{
    int n = blockIdx.x * 8 + (threadIdx.x >> 5);
    if (n >= NN) return;
    int lane = threadIdx.x & 31;
    int s0 = off[n], s1 = off[n + 1];
    float4 a0 = make_float4(0.f, 0.f, 0.f, 0.f), a1 = a0;
    for (int e = s0; e < s1; ++e) {
        int s = csr[e];
        const float4* hp = (const float4*)(h + (size_t)s * HD);
        float4 v0 = hp[lane], v1 = hp[lane + 32];
        a0.x += v0.x; a0.y += v0.y; a0.z += v0.z; a0.w += v0.w;
        a1.x += v1.x; a1.y += v1.y; a1.z += v1.z; a1.w += v1.w;
    }
    float inv = 1.f / (float)max(s1 - s0, 1);
    a0.x *= inv; a0.y *= inv; a0.z *= inv; a0.w *= inv;
    a1.x *= inv; a1.y *= inv; a1.z *= inv; a1.w *= inv;
    float4* mp = (float4*)(mean + (size_t)n * HD);
    mp[lane] = a0;
    mp[lane + 32] = a1;
}

// ---------------- fused ReLU + LayerNorm (warp per row, H=256) ---------------
__global__ __launch_bounds__(256) void relu_ln_kernel(
    const float* __restrict__ X, float* __restrict__ Y,
    const float* __restrict__ gamma, const float* __restrict__ beta, int M)
{
    int row = blockIdx.x * 8 + (threadIdx.x >> 5);
    if (row >= M) return;
    int lane = threadIdx.x & 31;
    const float* x = X + (size_t)row * HD;
    float v[8];
    float s = 0.f;
#pragma unroll
    for (int i = 0; i < 8; ++i) { v[i] = fmaxf(x[lane + 32 * i], 0.f); s += v[i]; }
#pragma unroll
    for (int o = 16; o; o >>= 1) s += __shfl_xor_sync(0xffffffffu, s, o);
    float mu = s * (1.f / HD);
    float q = 0.f;
#pragma unroll
    for (int i = 0; i < 8; ++i) { float d = v[i] - mu; q += d * d; }
#pragma unroll
    for (int o = 16; o; o >>= 1) q += __shfl_xor_sync(0xffffffffu, q, o);
    float rstd = rsqrtf(q * (1.f / HD) + 1e-5f);
    float* y = Y + (size_t)row * HD;
#pragma unroll
    for (int i = 0; i < 8; ++i) {
        int c = lane + 32 * i;
        y[c] = (v[i] - mu) * rstd * gamma[c] + beta[c];
    }
}

// ---------------- L2 row-normalize ------------------------------------------
__global__ __launch_bounds__(256) void l2norm_kernel(
    const float* __restrict__ X, float* __restrict__ Y, int M)
{
    int row = blockIdx.x * 8 + (threadIdx.x >> 5);
    if (row >= M) return;
    int lane = threadIdx.x & 31;
    const float* x = X + (size_t)row * HD;
    float v[8];
    float s = 0.f;
#pragma unroll
    for (int i = 0; i < 8; ++i) { v[i] = x[lane + 32 * i]; s += v[i] * v[i]; }
#pragma unroll
    for (int o = 16; o; o >>= 1) s += __shfl_xor_sync(0xffffffffu, s, o);
    float sc = 1.f / fmaxf(sqrtf(s), 1e-12f);
    float* y = Y + (size_t)row * HD;
#pragma unroll
    for (int i = 0; i < 8; ++i) y[lane + 32 * i] = v[i] * sc;
}

// ---------------- final logits ----------------------------------------------
__global__ __launch_bounds__(256) void logits_kernel(
    const float* __restrict__ z2, const float* __restrict__ W3,
    const float* __restrict__ b3, float* __restrict__ out)
{
    int p = blockIdx.x * 8 + (threadIdx.x >> 5);
    if (p >= PP) return;
    int lane = threadIdx.x & 31;
    const float* z = z2 + (size_t)p * HIDD;
    float s = 0.f;
#pragma unroll
    for (int i = 0; i < 4; ++i) { int c = lane + 32 * i; s += z[c] * W3[c]; }
#pragma unroll
    for (int o = 16; o; o >>= 1) s += __shfl_xor_sync(0xffffffffu, s, o);
    if (lane == 0) out[p] = s + b3[0];
}

// ---------------- launch ----------------------------------------------------
extern "C" void kernel_launch(void* const* d_in, const int* in_sizes, int n_in,
                              void* d_out, int out_size)
{
    const float* X       = (const float*)d_in[0];
    const int*   edge    = (const int*)d_in[1];
    const int*   i_idx   = (const int*)d_in[2];
    const int*   j_idx   = (const int*)d_in[3];
    const float* W_in    = (const float*)d_in[4];
    const float* b_in    = (const float*)d_in[5];
    const float* Ws_self = (const float*)d_in[6];
    const float* bs_self = (const float*)d_in[7];
    const float* Ws_nei  = (const float*)d_in[8];
    const float* bs_nei  = (const float*)d_in[9];
    const float* gammas  = (const float*)d_in[10];
    const float* betas   = (const float*)d_in[11];
    const float* W1      = (const float*)d_in[12];
    const float* b1      = (const float*)d_in[13];
    const float* W2      = (const float*)d_in[14];
    const float* b2      = (const float*)d_in[15];
    const float* W3      = (const float*)d_in[16];
    const float* b3      = (const float*)d_in[17];

    const int* src = edge;
    const int* dst = edge + EE;

    float *h, *tmp, *mean, *z1, *z2;
    int *cnt, *off, *cur, *csr;
    cudaGetSymbolAddress((void**)&h,    g_h);
    cudaGetSymbolAddress((void**)&tmp,  g_tmp);
    cudaGetSymbolAddress((void**)&mean, g_mean);
    cudaGetSymbolAddress((void**)&z1,   g_z1);
    cudaGetSymbolAddress((void**)&z2,   g_z2);
    cudaGetSymbolAddress((void**)&cnt,  g_cnt);
    cudaGetSymbolAddress((void**)&off,  g_off);
    cudaGetSymbolAddress((void**)&cur,  g_cur);
    cudaGetSymbolAddress((void**)&csr,  g_csr);

    float* outH = (float*)d_out;
    float* outL = outH + (size_t)NN * HD;

    dim3 blk(256);

    cudaFuncSetAttribute(tc_gemm<true, false, false>,
                         cudaFuncAttributeMaxDynamicSharedMemorySize, SMEM_TOT);
    cudaFuncSetAttribute(tc_gemm<false, true, false>,
                         cudaFuncAttributeMaxDynamicSharedMemorySize, SMEM_TOT);
    cudaFuncSetAttribute(tc_gemm<true, false, true>,
                         cudaFuncAttributeMaxDynamicSharedMemorySize, SMEM_TOT);

    // 1) encoder: h = relu(X @ W_in + b_in)
    tc_gemm<true, false, false><<<dim3(HD / 128, (NN + 127) / 128), blk, SMEM_TOT>>>(
        X, W_in, b_in, nullptr, nullptr, nullptr, nullptr, nullptr,
        h, NN, HD, IND);

    // 2) CSR build
    cudaMemsetAsync(cnt, 0, NN * sizeof(int));
    count_kernel<<<(EE + 255) / 256, blk>>>(dst, cnt);
    scan_kernel<<<1, 1024>>>(cnt, off, cur);
    fill_kernel<<<(EE + 255) / 256, blk>>>(src, dst, cur, csr);

    // 3) GNN layers
    for (int l = 0; l < 3; ++l) {
        agg_kernel<<<(NN + 7) / 8, blk>>>(off, csr, h, mean);
        tc_gemm<false, true, false><<<dim3(HD / 128, (NN + 127) / 128), blk, SMEM_TOT>>>(
            h, Ws_self + (size_t)l * HD * HD, bs_self + (size_t)l * HD,
            mean, Ws_nei + (size_t)l * HD * HD, bs_nei + (size_t)l * HD,
            nullptr, nullptr, tmp, NN, HD, HD);
        relu_ln_kernel<<<(NN + 7) / 8, blk>>>(tmp, h, gammas + (size_t)l * HD,
                                              betas + (size_t)l * HD, NN);
    }

    // 4) H = l2-normalize(h)
    l2norm_kernel<<<(NN + 7) / 8, blk>>>(h, outH, NN);

    // 5) edge head (feat fused into GEMM1 A-loader)
    tc_gemm<true, false, true><<<dim3(HIDD / 128, (PP + 127) / 128), blk, SMEM_TOT>>>(
        outH, W1, b1, nullptr, nullptr, nullptr, i_idx, j_idx,
        z1, PP, HIDD, 2 * HD);
    tc_gemm<true, false, false><<<dim3(HIDD / 128, (PP + 127) / 128), blk, SMEM_TOT>>>(
        z1, W2, b2, nullptr, nullptr, nullptr, nullptr, nullptr,
        z2, PP, HIDD, HIDD);
    logits_kernel<<<(PP + 7) / 8, blk>>>(z2, W3, b3, outL);
}

// round 17
// speedup vs baseline: 2.1341x; 1.0011x over previous
#include <cuda_runtime.h>

#define NN   50000
#define EE   300000
#define PP   200000
#define IND  480
#define HD   256
#define HIDD 128

// ---------------- scratch (device globals) ----------------------------------
__device__ float g_h[(size_t)NN * HD];
__device__ float g_tmp[(size_t)NN * HD];
__device__ float g_mean[(size_t)NN * HD];
__device__ float g_z1[(size_t)PP * HIDD];
__device__ float g_z2[(size_t)PP * HIDD];
__device__ int   g_cnt[NN];
__device__ int   g_off[NN + 1];
__device__ int   g_cur[NN];
__device__ int   g_csr[EE];

// ---------------- helpers ----------------------------------------------------
__device__ __forceinline__ unsigned smem_u32(const void* p) {
    unsigned r;
    asm("{ .reg .u64 t; cvta.to.shared.u64 t, %1; cvt.u32.u64 %0, t; }"
        : "=r"(r) : "l"(p));
    return r;
}

// pack two fp32 into (bf16x2 hi-pair, bf16x2 lo-pair); low half = x0
__device__ __forceinline__ uint2 bsplit2(float x0, float x1) {
    unsigned hp;
    asm("cvt.rn.bf16x2.f32 %0, %1, %2;" : "=r"(hp) : "f"(x1), "f"(x0));
    float h0 = __uint_as_float(hp << 16);
    float h1 = __uint_as_float(hp & 0xffff0000u);
    unsigned lp;
    asm("cvt.rn.bf16x2.f32 %0, %1, %2;" : "=r"(lp) : "f"(x1 - h1), "f"(x0 - h0));
    return make_uint2(hp, lp);
}

#define SWZ128(off) ((off) ^ (((off) >> 3) & 0x70))

// tcgen05 smem layout (dynamic smem): 2 stages of 64KB (A/B x hi/lo, 16KB each)
#define OFF_TMEM  0
#define OFF_MBAR  8           // two mbarriers: +0, +8
#define OFF_TILE  1024
#define STAGE_SZ  65536
#define T_AHI     0
#define T_ALO     16384
#define T_BHI     32768
#define T_BLO     49152
#define SMEM_TOT  (OFF_TILE + 2 * STAGE_SZ)

#if defined(__CUDA_ARCH__) && defined(__CUDA_ARCH_FEAT_SM103_ALL)
#define HAS_TCGEN05 1
#else
#define HAS_TCGEN05 0
#endif

#if HAS_TCGEN05
__device__ __forceinline__ unsigned elect1() {
    unsigned p;
    asm volatile("{\n\t.reg .pred p;\n\telect.sync _|p, 0xFFFFFFFF;\n\t"
                 "selp.b32 %0, 1, 0, p;\n\t}" : "=r"(p));
    return p;
}
__device__ __forceinline__ unsigned long long mk_desc(unsigned addr) {
    const unsigned long long base =
        (2ull << 61) | (1ull << 46) | (64ull << 32) | (1ull << 16);
    return base | ((unsigned long long)(addr >> 4) & 0x3FFFull);
}
__device__ __forceinline__ void mma_f16_ss(unsigned d, unsigned long long ad,
                                           unsigned long long bd, unsigned idesc,
                                           unsigned en) {
    asm volatile(
        "{\n\t.reg .pred p;\n\tsetp.ne.u32 p, %5, 0;\n\t"
        "tcgen05.mma.cta_group::1.kind::f16 [%0], %1, %2, %3, {%4,%4,%4,%4}, p;\n\t}"
        :: "r"(d), "l"(ad), "l"(bd), "r"(idesc), "r"(0u), "r"(en) : "memory");
}
__device__ __forceinline__ void mbar_wait(unsigned mbar, unsigned parity) {
    asm volatile(
        "{\n\t.reg .pred P;\n\tW%=:\n\t"
        "mbarrier.try_wait.parity.acquire.cta.shared::cta.b64 P, [%0], %1, 0x989680;\n\t"
        "@!P bra W%=;\n\t}" :: "r"(mbar), "r"(parity) : "memory");
}
#endif

// ---------------- GEMM: tcgen05 (sm_103a) or mma.sync fallback --------------
// C[M,Nc] = act( A@B + bias (+ A2@B2 + bias2 if DUAL) )
// FEAT: logical A row p = concat(|H[i]-H[j]|, H[i]*H[j]), K = 2*HD.
template <bool RELU, bool DUAL, bool FEAT>
__global__ __launch_bounds__(256) void tc_gemm(
    const float* __restrict__ A, const float* __restrict__ B,
    const float* __restrict__ bias,
    const float* __restrict__ A2, const float* __restrict__ B2,
    const float* __restrict__ bias2,
    const int* __restrict__ iidx, const int* __restrict__ jidx,
    float* __restrict__ C, int M, int Nc, int K)
{
#if HAS_TCGEN05
    // ====== tcgen05 path: 128x128 tile, SS bf16 3-term, 2-stage pipeline ====
    extern __shared__ char smem[];
    const unsigned sb = smem_u32(smem);
    const int tid = threadIdx.x;
    const int warp = tid >> 5, lane = tid & 31;
    const int bm = blockIdx.y * 128, bn = blockIdx.x * 128;

    const unsigned IDESC = (1u << 4) | (1u << 7) | (1u << 10) |
                           ((128u / 8) << 17) | ((128u / 16) << 24);

    if (warp == 4) {
        asm volatile(
            "tcgen05.alloc.cta_group::1.sync.aligned.shared::cta.b32 [%0], %1;"
            :: "r"(sb + OFF_TMEM), "r"(128u) : "memory");
    }
    if (tid == 0) {
        asm volatile("mbarrier.init.shared.b64 [%0], %1;"
                     :: "r"(sb + OFF_MBAR), "r"(1u) : "memory");
        asm volatile("mbarrier.init.shared.b64 [%0], %1;"
                     :: "r"(sb + OFF_MBAR + 8), "r"(1u) : "memory");
    }
    __syncthreads();
    unsigned tmem;
    asm volatile("ld.shared.b32 %0, [%1];" : "=r"(tmem) : "r"(sb + OFF_TMEM));

    const int nCh = (K + 63) >> 6;
    const int nIter = (DUAL ? 2 : 1) * nCh;

    const int am = tid >> 1, ah = (tid & 1) * 32;
    const int arow = bm + am;
    int ia = 0, jb = 0;
    if (FEAT && arow < M) { ia = iidx[arow]; jb = jidx[arow]; }
    const int bnn = tid & 127, bkh = (tid >> 7) * 32;

    for (int it = 0; it < nIter; ++it) {
        const int part = DUAL ? (it / nCh) : 0;
        const int k0 = (it - part * nCh) * 64;
        const float* Ap = (DUAL && part) ? A2 : A;
        const float* Bp = (DUAL && part) ? B2 : B;
        const unsigned stg = sb + OFF_TILE + (unsigned)(it & 1) * STAGE_SZ;
        char* stp = smem + OFF_TILE + (size_t)(it & 1) * STAGE_SZ;

        // ---- global loads into registers ----
        float a[32];
        {
            const bool valid = (arow < M) && (k0 + ah < K);
            if (valid) {
                if (FEAT) {
                    const float* Ha = A + (size_t)ia * HD;
                    const float* Hb = A + (size_t)jb * HD;
#pragma unroll
                    for (int q = 0; q < 8; ++q) {
                        int kg = k0 + ah + q * 4;
                        float4 xa, xb, r;
                        if (kg < HD) {
                            xa = *(const float4*)(Ha + kg);
                            xb = *(const float4*)(Hb + kg);
                            r = make_float4(fabsf(xa.x - xb.x), fabsf(xa.y - xb.y),
                                            fabsf(xa.z - xb.z), fabsf(xa.w - xb.w));
                        } else {
                            xa = *(const float4*)(Ha + kg - HD);
                            xb = *(const float4*)(Hb + kg - HD);
                            r = make_float4(xa.x * xb.x, xa.y * xb.y,
                                            xa.z * xb.z, xa.w * xb.w);
                        }
                        a[q * 4 + 0] = r.x; a[q * 4 + 1] = r.y;
                        a[q * 4 + 2] = r.z; a[q * 4 + 3] = r.w;
                    }
                } else {
                    const float* p = Ap + (size_t)arow * K + k0 + ah;
#pragma unroll
                    for (int q = 0; q < 8; ++q) {
                        float4 v = *(const float4*)(p + q * 4);
                        a[q * 4 + 0] = v.x; a[q * 4 + 1] = v.y;
                        a[q * 4 + 2] = v.z; a[q * 4 + 3] = v.w;
                    }
                }
            } else {
#pragma unroll
                for (int q = 0; q < 32; ++q) a[q] = 0.f;
            }
        }
        float b[32];
        {
            const bool valid = (k0 + bkh < K);
            if (valid) {
                const float* p = Bp + (size_t)(k0 + bkh) * Nc + bn + bnn;
#pragma unroll
                for (int q = 0; q < 32; ++q) b[q] = p[(size_t)q * Nc];
            } else {
#pragma unroll
                for (int q = 0; q < 32; ++q) b[q] = 0.f;
            }
        }

        // ---- wait for this stage's previous MMAs (2 iterations of slack) ----
        if (it >= 2)
            mbar_wait(sb + OFF_MBAR + (it & 1) * 8, ((it >> 1) - 1) & 1);

        // ---- split + swizzled stores into this stage ----
#pragma unroll
        for (int g = 0; g < 4; ++g) {
            uint2 p0 = bsplit2(a[g * 8 + 0], a[g * 8 + 1]);
            uint2 p1 = bsplit2(a[g * 8 + 2], a[g * 8 + 3]);
            uint2 p2 = bsplit2(a[g * 8 + 4], a[g * 8 + 5]);
            uint2 p3 = bsplit2(a[g * 8 + 6], a[g * 8 + 7]);
            unsigned off = (unsigned)(am * 128 + (ah + g * 8) * 2);
            unsigned sw = SWZ128(off);
            *(uint4*)(stp + T_AHI + sw) = make_uint4(p0.x, p1.x, p2.x, p3.x);
            *(uint4*)(stp + T_ALO + sw) = make_uint4(p0.y, p1.y, p2.y, p3.y);
        }
#pragma unroll
        for (int g = 0; g < 4; ++g) {
            uint2 p0 = bsplit2(b[g * 8 + 0], b[g * 8 + 1]);
            uint2 p1 = bsplit2(b[g * 8 + 2], b[g * 8 + 3]);
            uint2 p2 = bsplit2(b[g * 8 + 4], b[g * 8 + 5]);
            uint2 p3 = bsplit2(b[g * 8 + 6], b[g * 8 + 7]);
            unsigned off = (unsigned)(bnn * 128 + (bkh + g * 8) * 2);
            unsigned sw = SWZ128(off);
            *(uint4*)(stp + T_BHI + sw) = make_uint4(p0.x, p1.x, p2.x, p3.x);
            *(uint4*)(stp + T_BLO + sw) = make_uint4(p0.y, p1.y, p2.y, p3.y);
        }
        asm volatile("fence.proxy.async.shared::cta;" ::: "memory");
        __syncthreads();

        // ---- issue 12 MMAs for this stage; commit to stage barrier ----
        if (warp == 4) {
            if (elect1()) {
                unsigned long long dAh = mk_desc(stg + T_AHI);
                unsigned long long dAl = mk_desc(stg + T_ALO);
                unsigned long long dBh = mk_desc(stg + T_BHI);
                unsigned long long dBl = mk_desc(stg + T_BLO);
#pragma unroll
                for (int ks = 0; ks < 4; ++ks) {
                    unsigned en0 = (it > 0 || ks > 0) ? 1u : 0u;
                    mma_f16_ss(tmem, dAh + ks * 2, dBh + ks * 2, IDESC, en0);
                    mma_f16_ss(tmem, dAl + ks * 2, dBh + ks * 2, IDESC, 1u);
                    mma_f16_ss(tmem, dAh + ks * 2, dBl + ks * 2, IDESC, 1u);
                }
                asm volatile(
                    "tcgen05.commit.cta_group::1.mbarrier::arrive::one.shared::cluster.b64 [%0];"
                    :: "r"(sb + OFF_MBAR + (it & 1) * 8) : "memory");
            }
        }
    }

    // ---- wait for final commit (covers all prior MMAs), epilogue ----
    mbar_wait(sb + OFF_MBAR + ((nIter - 1) & 1) * 8, ((nIter - 1) >> 1) & 1);
    asm volatile("tcgen05.fence::after_thread_sync;" ::: "memory");

    if (warp < 4) {
        int m = bm + warp * 32 + lane;
#pragma unroll
        for (int half = 0; half < 2; ++half) {
            unsigned d[64];
            asm volatile(
                "tcgen05.ld.sync.aligned.32x32b.x32.b32 "
                "{%0,%1,%2,%3,%4,%5,%6,%7,%8,%9,%10,%11,%12,%13,%14,%15,"
                "%16,%17,%18,%19,%20,%21,%22,%23,%24,%25,%26,%27,%28,%29,%30,%31}, [%32];"
                : "=r"(d[0]), "=r"(d[1]), "=r"(d[2]), "=r"(d[3]), "=r"(d[4]),
                  "=r"(d[5]), "=r"(d[6]), "=r"(d[7]), "=r"(d[8]), "=r"(d[9]),
                  "=r"(d[10]), "=r"(d[11]), "=r"(d[12]), "=r"(d[13]), "=r"(d[14]),
                  "=r"(d[15]), "=r"(d[16]), "=r"(d[17]), "=r"(d[18]), "=r"(d[19]),
                  "=r"(d[20]), "=r"(d[21]), "=r"(d[22]), "=r"(d[23]), "=r"(d[24]),
                  "=r"(d[25]), "=r"(d[26]), "=r"(d[27]), "=r"(d[28]), "=r"(d[29]),
                  "=r"(d[30]), "=r"(d[31])
                : "r"(tmem + half * 64));
            asm volatile(
                "tcgen05.ld.sync.aligned.32x32b.x32.b32 "
                "{%0,%1,%2,%3,%4,%5,%6,%7,%8,%9,%10,%11,%12,%13,%14,%15,"
                "%16,%17,%18,%19,%20,%21,%22,%23,%24,%25,%26,%27,%28,%29,%30,%31}, [%32];"
                : "=r"(d[32]), "=r"(d[33]), "=r"(d[34]), "=r"(d[35]), "=r"(d[36]),
                  "=r"(d[37]), "=r"(d[38]), "=r"(d[39]), "=r"(d[40]), "=r"(d[41]),
                  "=r"(d[42]), "=r"(d[43]), "=r"(d[44]), "=r"(d[45]), "=r"(d[46]),
                  "=r"(d[47]), "=r"(d[48]), "=r"(d[49]), "=r"(d[50]), "=r"(d[51]),
                  "=r"(d[52]), "=r"(d[53]), "=r"(d[54]), "=r"(d[55]), "=r"(d[56]),
                  "=r"(d[57]), "=r"(d[58]), "=r"(d[59]), "=r"(d[60]), "=r"(d[61]),
                  "=r"(d[62]), "=r"(d[63])
                : "r"(tmem + half * 64 + 32));
            asm volatile("tcgen05.wait::ld.sync.aligned;" ::: "memory");
            if (m < M) {
#pragma unroll
                for (int c4 = 0; c4 < 16; ++c4) {
                    int col = bn + half * 64 + c4 * 4;
                    float v0 = __uint_as_float(d[c4 * 4 + 0]) + bias[col + 0];
                    float v1 = __uint_as_float(d[c4 * 4 + 1]) + bias[col + 1];
                    float v2 = __uint_as_float(d[c4 * 4 + 2]) + bias[col + 2];
                    float v3 = __uint_as_float(d[c4 * 4 + 3]) + bias[col + 3];
                    if (DUAL) {
                        v0 += bias2[col + 0]; v1 += bias2[col + 1];
                        v2 += bias2[col + 2]; v3 += bias2[col + 3];
                    }
                    if (RELU) {
                        v0 = fmaxf(v0, 0.f); v1 = fmaxf(v1, 0.f);
                        v2 = fmaxf(v2, 0.f); v3 = fmaxf(v3, 0.f);
                    }
                    *(float4*)(C + (size_t)m * Nc + col) = make_float4(v0, v1, v2, v3);
                }
            }
        }
    }
    __syncthreads();
    if (tid == 0) {
        asm volatile("mbarrier.inval.shared.b64 [%0];"
                     :: "r"(sb + OFF_MBAR) : "memory");
        asm volatile("mbarrier.inval.shared.b64 [%0];"
                     :: "r"(sb + OFF_MBAR + 8) : "memory");
    }
    if (warp == 4) {
        asm volatile("tcgen05.dealloc.cta_group::1.sync.aligned.b32 %0, %1;"
                     :: "r"(tmem), "r"(128u));
    }
#else
    // ================= fallback: proven mma.sync bf16 3-term (round 10) =====
    constexpr int PA = 12;
    constexpr int PB = 132;
    __shared__ uint2 As[128][PA];
    __shared__ uint2 Bs[8][PB];

    const int tid  = threadIdx.x;
    const int warp = tid >> 5, lane = tid & 31;
    const int group = lane >> 2, tig = lane & 3;
    const int wm = (warp & 3) * 32, wn = (warp >> 2) * 64;
    const int bm = blockIdx.y * 128, bn = blockIdx.x * 128;

    const int kIters = K / 16;
    const int nIter = (DUAL ? 2 : 1) * kIters;

    const int am = tid >> 1, akq = (tid & 1) * 8;
    const int arow = bm + am;
    int ia = 0, jb = 0;
    if (FEAT && arow < M) { ia = iidx[arow]; jb = jidx[arow]; }
    const int bkp = tid >> 5;
    const int bc0 = (tid & 31) * 4;

    float c[2][8][4] = {};

    for (int it = 0; it < nIter; ++it) {
        const int part = DUAL ? (it / kIters) : 0;
        const int k0 = (it - part * kIters) * 16;

        {
            float ra[8];
#pragma unroll
            for (int q = 0; q < 8; ++q) ra[q] = 0.f;
            if (arow < M) {
                if (FEAT) {
                    const float* Ha = A + (size_t)ia * HD;
                    const float* Hb = A + (size_t)jb * HD;
                    int k = k0 + akq;
#pragma unroll
                    for (int q = 0; q < 2; ++q) {
                        int kk = k + q * 4;
                        float4 r;
                        if (kk < HD) {
                            float4 xa = *(const float4*)(Ha + kk);
                            float4 xb = *(const float4*)(Hb + kk);
                            r = make_float4(fabsf(xa.x - xb.x), fabsf(xa.y - xb.y),
                                            fabsf(xa.z - xb.z), fabsf(xa.w - xb.w));
                        } else {
                            float4 xa = *(const float4*)(Ha + kk - HD);
                            float4 xb = *(const float4*)(Hb + kk - HD);
                            r = make_float4(xa.x * xb.x, xa.y * xb.y,
                                            xa.z * xb.z, xa.w * xb.w);
                        }
                        ra[q * 4 + 0] = r.x; ra[q * 4 + 1] = r.y;
                        ra[q * 4 + 2] = r.z; ra[q * 4 + 3] = r.w;
                    }
                } else {
                    const float* Ap = (DUAL && part) ? A2 : A;
                    const float* p = Ap + (size_t)arow * K + k0 + akq;
                    float4 v0 = *(const float4*)p;
                    float4 v1 = *(const float4*)(p + 4);
                    ra[0] = v0.x; ra[1] = v0.y; ra[2] = v0.z; ra[3] = v0.w;
                    ra[4] = v1.x; ra[5] = v1.y; ra[6] = v1.z; ra[7] = v1.w;
                }
            }
            uint2 s0 = bsplit2(ra[0], ra[1]);
            uint2 s1 = bsplit2(ra[2], ra[3]);
            uint2 s2 = bsplit2(ra[4], ra[5]);
            uint2 s3 = bsplit2(ra[6], ra[7]);
            uint4* dp = (uint4*)&As[am][(tid & 1) * 4];
            dp[0] = make_uint4(s0.x, s0.y, s1.x, s1.y);
            dp[1] = make_uint4(s2.x, s2.y, s3.x, s3.y);
        }
        {
            const float* Bp = (DUAL && part) ? B2 : B;
            const float* p0 = Bp + (size_t)(k0 + 2 * bkp) * Nc + bn + bc0;
            const float* p1 = p0 + Nc;
            float4 r0 = *(const float4*)p0;
            float4 r1 = *(const float4*)p1;
            uint2 s0 = bsplit2(r0.x, r1.x);
            uint2 s1 = bsplit2(r0.y, r1.y);
            uint2 s2 = bsplit2(r0.z, r1.z);
            uint2 s3 = bsplit2(r0.w, r1.w);
            uint4* dp = (uint4*)&Bs[bkp][bc0];
            dp[0] = make_uint4(s0.x, s0.y, s1.x, s1.y);
            dp[1] = make_uint4(s2.x, s2.y, s3.x, s3.y);
        }
        __syncthreads();

        {
            uint2 af[2][4];
#pragma unroll
            for (int i = 0; i < 2; ++i) {
                int r = wm + i * 16 + group;
                af[i][0] = As[r][tig];
                af[i][1] = As[r + 8][tig];
                af[i][2] = As[r][tig + 4];
                af[i][3] = As[r + 8][tig + 4];
            }
            uint2 bf[8][2];
#pragma unroll
            for (int j = 0; j < 8; ++j) {
                int nc_ = wn + j * 8 + group;
                bf[j][0] = Bs[tig][nc_];
                bf[j][1] = Bs[tig + 4][nc_];
            }
#pragma unroll
            for (int i = 0; i < 2; ++i)
#pragma unroll
                for (int j = 0; j < 8; ++j) {
                    asm volatile(
                        "mma.sync.aligned.m16n8k16.row.col.f32.bf16.bf16.f32 "
                        "{%0,%1,%2,%3},{%4,%5,%6,%7},{%8,%9},{%0,%1,%2,%3};"
                        : "+f"(c[i][j][0]), "+f"(c[i][j][1]),
                          "+f"(c[i][j][2]), "+f"(c[i][j][3])
                        : "r"(af[i][0].x), "r"(af[i][1].x), "r"(af[i][2].x), "r"(af[i][3].x),
                          "r"(bf[j][0].x), "r"(bf[j][1].x));
                    asm volatile(
                        "mma.sync.aligned.m16n8k16.row.col.f32.bf16.bf16.f32 "
                        "{%0,%1,%2,%3},{%4,%5,%6,%7},{%8,%9},{%0,%1,%2,%3};"
                        : "+f"(c[i][j][0]), "+f"(c[i][j][1]),
                          "+f"(c[i][j][2]), "+f"(c[i][j][3])
                        : "r"(af[i][0].y), "r"(af[i][1].y), "r"(af[i][2].y), "r"(af[i][3].y),
                          "r"(bf[j][0].x), "r"(bf[j][1].x));
                    asm volatile(
                        "mma.sync.aligned.m16n8k16.row.col.f32.bf16.bf16.f32 "
                        "{%0,%1,%2,%3},{%4,%5,%6,%7},{%8,%9},{%0,%1,%2,%3};"
                        : "+f"(c[i][j][0]), "+f"(c[i][j][1]),
                          "+f"(c[i][j][2]), "+f"(c[i][j][3])
                        : "r"(af[i][0].x), "r"(af[i][1].x), "r"(af[i][2].x), "r"(af[i][3].x),
                          "r"(bf[j][0].y), "r"(bf[j][1].y));
                }
        }
        __syncthreads();
    }

#pragma unroll
    for (int i = 0; i < 2; ++i) {
        int r0 = bm + wm + i * 16 + group;
#pragma unroll
        for (int j = 0; j < 8; ++j) {
            int col = bn + wn + j * 8 + tig * 2;
            float bb0 = bias[col], bb1 = bias[col + 1];
            if (DUAL) { bb0 += bias2[col]; bb1 += bias2[col + 1]; }
            if (r0 < M) {
                float v0 = c[i][j][0] + bb0, v1 = c[i][j][1] + bb1;
                if (RELU) { v0 = fmaxf(v0, 0.f); v1 = fmaxf(v1, 0.f); }
                C[(size_t)r0 * Nc + col] = v0;
                C[(size_t)r0 * Nc + col + 1] = v1;
            }
            if (r0 + 8 < M) {
                float v2 = c[i][j][2] + bb0, v3 = c[i][j][3] + bb1;
                if (RELU) { v2 = fmaxf(v2, 0.f); v3 = fmaxf(v3, 0.f); }
                C[(size_t)(r0 + 8) * Nc + col] = v2;
                C[(size_t)(r0 + 8) * Nc + col + 1] = v3;
            }
        }
    }
#endif
}

// ---------------- CSR build --------------------------------------------------
__global__ __launch_bounds__(256) void count_kernel(const int* __restrict__ dst,
                                                    int* __restrict__ cnt)
{
    int e = blockIdx.x * blockDim.x + threadIdx.x;
    if (e < EE) atomicAdd(&cnt[dst[e]], 1);
}

__global__ __launch_bounds__(1024) void scan_kernel(const int* __restrict__ cnt,
                                                    int* __restrict__ off,
                                                    int* __restrict__ cur)
{
    __shared__ int sh[1024];
    __shared__ int carry;
    int t = threadIdx.x;
    if (t == 0) carry = 0;
    __syncthreads();
    for (int base = 0; base < NN; base += 1024) {
        int i = base + t;
        int v = (i < NN) ? cnt[i] : 0;
        sh[t] = v;
        __syncthreads();
        for (int o = 1; o < 1024; o <<= 1) {
            int x = (t >= o) ? sh[t - o] : 0;
            __syncthreads();
            sh[t] += x;
            __syncthreads();
        }
        int excl = sh[t] - v;
        if (i < NN) { off[i] = carry + excl; cur[i] = carry + excl; }
        __syncthreads();
        if (t == 0) carry += sh[1023];
        __syncthreads();
    }
    if (t == 0) off[NN] = carry;
}

__global__ __launch_bounds__(256) void fill_kernel(const int* __restrict__ src,
                                                   const int* __restrict__ dst,
                                                   int* __restrict__ cur,
                                                   int* __restrict__ csr)
{
    int e = blockIdx.x * blockDim.x + threadIdx.x;
    if (e < EE) {
        int d = dst[e];
        int pos = atomicAdd(&cur[d], 1);
        csr[pos] = src[e];
    }
}

// ---------------- neighbor mean (warp per node, CSR gather) ------------------
__global__ __launch_bounds__(256) void agg_kernel(
    const int* __restrict__ off, const int* __restrict__ csr,
    const float* __restrict__ h, float* __restrict__ mean)
{
    int n = blockIdx.x * 8 + (threadIdx.x >> 5);
    if (n >= NN) return;
    int lane = threadIdx.x & 31;
    int s0 = off[n], s1 = off[n + 1];
    float4 a0 = make_float4(0.f, 0.f, 0.f, 0.f), a1 = a0;
    for (int e = s0; e < s1; ++e) {
        int s = csr[e];
        const float4* hp = (const float4*)(h + (size_t)s * HD);
        float4 v0 = hp[lane], v1 = hp[lane + 32];
        a0.x += v0.x; a0.y += v0.y; a0.z += v0.z; a0.w += v0.w;
        a1.x += v1.x; a1.y += v1.y; a1.z += v1.z; a1.w += v1.w;
    }
    float inv = 1.f / (float)max(s1 - s0, 1);
    a0.x *= inv; a0.y *= inv; a0.z *= inv; a0.w *= inv;
    a1.x *= inv; a1.y *= inv; a1.z *= inv; a1.w *= inv;
    float4* mp = (float4*)(mean + (size_t)n * HD);
    mp[lane] = a0;
    mp[lane + 32] = a1;
}

// ---------------- fused ReLU + LayerNorm (warp per row, H=256) ---------------
__global__ __launch_bounds__(256) void relu_ln_kernel(
    const float* __restrict__ X, float* __restrict__ Y,
    const float* __restrict__ gamma, const float* __restrict__ beta, int M)
{
    int row = blockIdx.x * 8 + (threadIdx.x >> 5);
    if (row >= M) return;
    int lane = threadIdx.x & 31;
    const float* x = X + (size_t)row * HD;
    float v[8];
    float s = 0.f;
#pragma unroll
    for (int i = 0; i < 8; ++i) { v[i] = fmaxf(x[lane + 32 * i], 0.f); s += v[i]; }
#pragma unroll
    for (int o = 16; o; o >>= 1) s += __shfl_xor_sync(0xffffffffu, s, o);
    float mu = s * (1.f / HD);
    float q = 0.f;
#pragma unroll
    for (int i = 0; i < 8; ++i) { float d = v[i] - mu; q += d * d; }
#pragma unroll
    for (int o = 16; o; o >>= 1) q += __shfl_xor_sync(0xffffffffu, q, o);
    float rstd = rsqrtf(q * (1.f / HD) + 1e-5f);
    float* y = Y + (size_t)row * HD;
#pragma unroll
    for (int i = 0; i < 8; ++i) {
        int c = lane + 32 * i;
        y[c] = (v[i] - mu) * rstd * gamma[c] + beta[c];
    }
}

// ---------------- L2 row-normalize ------------------------------------------
__global__ __launch_bounds__(256) void l2norm_kernel(
    const float* __restrict__ X, float* __restrict__ Y, int M)
{
    int row = blockIdx.x * 8 + (threadIdx.x >> 5);
    if (row >= M) return;
    int lane = threadIdx.x & 31;
    const float* x = X + (size_t)row * HD;
    float v[8];
    float s = 0.f;
#pragma unroll
    for (int i = 0; i < 8; ++i) { v[i] = x[lane + 32 * i]; s += v[i] * v[i]; }
#pragma unroll
    for (int o = 16; o; o >>= 1) s += __shfl_xor_sync(0xffffffffu, s, o);
    float sc = 1.f / fmaxf(sqrtf(s), 1e-12f);
    float* y = Y + (size_t)row * HD;
#pragma unroll
    for (int i = 0; i < 8; ++i) y[lane + 32 * i] = v[i] * sc;
}

// ---------------- final logits ----------------------------------------------
__global__ __launch_bounds__(256) void logits_kernel(
    const float* __restrict__ z2, const float* __restrict__ W3,
    const float* __restrict__ b3, float* __restrict__ out)
{
    int p = blockIdx.x * 8 + (threadIdx.x >> 5);
    if (p >= PP) return;
    int lane = threadIdx.x & 31;
    const float* z = z2 + (size_t)p * HIDD;
    float s = 0.f;
#pragma unroll
    for (int i = 0; i < 4; ++i) { int c = lane + 32 * i; s += z[c] * W3[c]; }
#pragma unroll
    for (int o = 16; o; o >>= 1) s += __shfl_xor_sync(0xffffffffu, s, o);
    if (lane == 0) out[p] = s + b3[0];
}

// ---------------- launch ----------------------------------------------------
extern "C" void kernel_launch(void* const* d_in, const int* in_sizes, int n_in,
                              void* d_out, int out_size)
{
    const float* X       = (const float*)d_in[0];
    const int*   edge    = (const int*)d_in[1];
    const int*   i_idx   = (const int*)d_in[2];
    const int*   j_idx   = (const int*)d_in[3];
    const float* W_in    = (const float*)d_in[4];
    const float* b_in    = (const float*)d_in[5];
    const float* Ws_self = (const float*)d_in[6];
    const float* bs_self = (const float*)d_in[7];
    const float* Ws_nei  = (const float*)d_in[8];
    const float* bs_nei  = (const float*)d_in[9];
    const float* gammas  = (const float*)d_in[10];
    const float* betas   = (const float*)d_in[11];
    const float* W1      = (const float*)d_in[12];
    const float* b1      = (const float*)d_in[13];
    const float* W2      = (const float*)d_in[14];
    const float* b2      = (const float*)d_in[15];
    const float* W3      = (const float*)d_in[16];
    const float* b3      = (const float*)d_in[17];

    const int* src = edge;
    const int* dst = edge + EE;

    float *h, *tmp, *mean, *z1, *z2;
    int *cnt, *off, *cur, *csr;
    cudaGetSymbolAddress((void**)&h,    g_h);
    cudaGetSymbolAddress((void**)&tmp,  g_tmp);
    cudaGetSymbolAddress((void**)&mean, g_mean);
    cudaGetSymbolAddress((void**)&z1,   g_z1);
    cudaGetSymbolAddress((void**)&z2,   g_z2);
    cudaGetSymbolAddress((void**)&cnt,  g_cnt);
    cudaGetSymbolAddress((void**)&off,  g_off);
    cudaGetSymbolAddress((void**)&cur,  g_cur);
    cudaGetSymbolAddress((void**)&csr,  g_csr);

    float* outH = (float*)d_out;
    float* outL = outH + (size_t)NN * HD;

    dim3 blk(256);

    cudaFuncSetAttribute(tc_gemm<true, false, false>,
                         cudaFuncAttributeMaxDynamicSharedMemorySize, SMEM_TOT);
    cudaFuncSetAttribute(tc_gemm<false, true, false>,
                         cudaFuncAttributeMaxDynamicSharedMemorySize, SMEM_TOT);
    cudaFuncSetAttribute(tc_gemm<true, false, true>,
                         cudaFuncAttributeMaxDynamicSharedMemorySize, SMEM_TOT);

    // 1) encoder: h = relu(X @ W_in + b_in)
    tc_gemm<true, false, false><<<dim3(HD / 128, (NN + 127) / 128), blk, SMEM_TOT>>>(
        X, W_in, b_in, nullptr, nullptr, nullptr, nullptr, nullptr,
        h, NN, HD, IND);

    // 2) CSR build
    cudaMemsetAsync(cnt, 0, NN * sizeof(int));
    count_kernel<<<(EE + 255) / 256, blk>>>(dst, cnt);
    scan_kernel<<<1, 1024>>>(cnt, off, cur);
    fill_kernel<<<(EE + 255) / 256, blk>>>(src, dst, cur, csr);

    // 3) GNN layers
    for (int l = 0; l < 3; ++l) {
        agg_kernel<<<(NN + 7) / 8, blk>>>(off, csr, h, mean);
        tc_gemm<false, true, false><<<dim3(HD / 128, (NN + 127) / 128), blk, SMEM_TOT>>>(
            h, Ws_self + (size_t)l * HD * HD, bs_self + (size_t)l * HD,
            mean, Ws_nei + (size_t)l * HD * HD, bs_nei + (size_t)l * HD,
            nullptr, nullptr, tmp, NN, HD, HD);
        relu_ln_kernel<<<(NN + 7) / 8, blk>>>(tmp, h, gammas + (size_t)l * HD,
                                              betas + (size_t)l * HD, NN);
    }

    // 4) H = l2-normalize(h)
    l2norm_kernel<<<(NN + 7) / 8, blk>>>(h, outH, NN);

    // 5) edge head (feat fused into GEMM1 A-loader)
    tc_gemm<true, false, true><<<dim3(HIDD / 128, (PP + 127) / 128), blk, SMEM_TOT>>>(
        outH, W1, b1, nullptr, nullptr, nullptr, i_idx, j_idx,
        z1, PP, HIDD, 2 * HD);
    tc_gemm<true, false, false><<<dim3(HIDD / 128, (PP + 127) / 128), blk, SMEM_TOT>>>(
        z1, W2, b2, nullptr, nullptr, nullptr, nullptr, nullptr,
        z2, PP, HIDD, HIDD);
    logits_kernel<<<(PP + 7) / 8, blk>>>(z2, W3, b3, outL);
}